// round 2
// baseline (speedup 1.0000x reference)
#include <cuda_runtime.h>
#include <cstdint>

// Problem constants (from reference)
#define C_N0 200000
#define C_N1 50000
#define C_N2 10000
#define C_INF 128
#define C_HID 128
#define C_RANK 64
#define C_OUTC 64

// ---------------- scratch (device globals; no allocation) ----------------
__device__ float g_hsrc1[(size_t)C_N0 * C_RANK];   // 51.2 MB
__device__ float g_agg1 [(size_t)C_N1 * C_RANK];   // 12.8 MB
__device__ int   g_cnt1 [C_N1];
__device__ float g_z    [(size_t)C_N1 * C_RANK];   // z1 (reused for z2)
__device__ float g_h    [(size_t)C_N1 * C_HID];    // 25.6 MB
__device__ float g_hsrc2[(size_t)C_N1 * C_RANK];
__device__ float g_agg2 [(size_t)C_N2 * C_RANK];
__device__ int   g_cnt2 [C_N2];

// ---------------- zero kernels ----------------
__global__ void zero_f(float* __restrict__ p, int n) {
    int i = blockIdx.x * blockDim.x + threadIdx.x;
    if (i < n) p[i] = 0.0f;
}
__global__ void zero_i(int* __restrict__ p, int n) {
    int i = blockIdx.x * blockDim.x + threadIdx.x;
    if (i < n) p[i] = 0;
}

// ---------------- tiled GEMM: C[M,N] = A[M,K] @ B[K,N] (+ epilogue) ------
// Tile 64x64, 256 threads, 4x4 per thread. K <= 128, K % 16 == 0, N % 64 == 0.
// MUL_AGG: C *= agg[row, col] / max(cnt[row],1)   (only used when N==64, single col tile)
// BIAS:    C += bias[col];  RELU: C = max(C, 0)
template <bool MUL_AGG, bool BIAS, bool RELU>
__global__ void gemm_kernel(const float* __restrict__ A,
                            const float* __restrict__ B,
                            float* __restrict__ C,
                            const float* __restrict__ agg,
                            const int*   __restrict__ cnt,
                            const float* __restrict__ bias,
                            int M, int K, int N)
{
    __shared__ float Bs[128 * 64];     // full K panel of the 64-col slice
    __shared__ float As[16][68];       // [k][row], pad 4 -> 16B-aligned float4 rows

    const int row0 = blockIdx.x * 64;
    const int col0 = blockIdx.y * 64;
    const int t    = threadIdx.x;
    const int tx   = t & 15;           // col group: cols tx*4 .. tx*4+3
    const int ty   = t >> 4;           // row group: rows ty*4 .. ty*4+3

    // Load B panel once: Bs[k*64+n] = B[k*N + col0 + n]
    for (int i = t; i < K * 64; i += 256) {
        int k = i >> 6, n = i & 63;
        Bs[i] = B[(size_t)k * N + col0 + n];
    }

    float acc[4][4] = {};

    const int ks    = t & 15;          // k within chunk for staging
    const int rbase = t >> 4;          // base row for staging

    __syncthreads();

    for (int kk = 0; kk < K; kk += 16) {
        // stage A chunk (transposed): As[k][r] = A[row0+r][kk+k]
        #pragma unroll
        for (int i = 0; i < 4; i++) {
            int r = rbase + i * 16;
            int gr = row0 + r;
            As[ks][r] = (gr < M) ? A[(size_t)gr * K + kk + ks] : 0.0f;
        }
        __syncthreads();

        #pragma unroll
        for (int k = 0; k < 16; k++) {
            float4 a = *(const float4*)&As[k][ty * 4];
            float4 b = *(const float4*)&Bs[(kk + k) * 64 + tx * 4];  // FIXED: advance B with kk
            acc[0][0] += a.x * b.x; acc[0][1] += a.x * b.y; acc[0][2] += a.x * b.z; acc[0][3] += a.x * b.w;
            acc[1][0] += a.y * b.x; acc[1][1] += a.y * b.y; acc[1][2] += a.y * b.z; acc[1][3] += a.y * b.w;
            acc[2][0] += a.z * b.x; acc[2][1] += a.z * b.y; acc[2][2] += a.z * b.z; acc[2][3] += a.z * b.w;
            acc[3][0] += a.w * b.x; acc[3][1] += a.w * b.y; acc[3][2] += a.w * b.z; acc[3][3] += a.w * b.w;
        }
        __syncthreads();
    }

    // epilogue
    #pragma unroll
    for (int i = 0; i < 4; i++) {
        int r = row0 + ty * 4 + i;
        if (r >= M) continue;
        float4 v = make_float4(acc[i][0], acc[i][1], acc[i][2], acc[i][3]);
        if (MUL_AGG) {
            float s = 1.0f / fmaxf((float)cnt[r], 1.0f);
            const float4 g = *(const float4*)&agg[(size_t)r * 64 + tx * 4];
            v.x *= g.x * s; v.y *= g.y * s; v.z *= g.z * s; v.w *= g.w * s;
        }
        if (BIAS) {
            const float4 bb = *(const float4*)&bias[col0 + tx * 4];
            v.x += bb.x; v.y += bb.y; v.z += bb.z; v.w += bb.w;
        }
        if (RELU) {
            v.x = fmaxf(v.x, 0.0f); v.y = fmaxf(v.y, 0.0f);
            v.z = fmaxf(v.z, 0.0f); v.w = fmaxf(v.w, 0.0f);
        }
        *(float4*)&C[(size_t)r * N + col0 + tx * 4] = v;
    }
}

// ---------------- edge scatter: agg[dst] += hsrc[src]; cnt[dst] += 1 -----
// 16 lanes per edge, each lane handles one float4 (coalesced 256B gather,
// vectorized v4.f32 global reduction -> 4x fewer L2 atomic ops).
__global__ void edge_scatter(const float* __restrict__ hsrc,
                             const int*   __restrict__ src,
                             const int*   __restrict__ dst,
                             float* __restrict__ agg,
                             int*   __restrict__ cnt,
                             int E)
{
    int tid  = blockIdx.x * blockDim.x + threadIdx.x;
    int e    = tid >> 4;
    int lane = tid & 15;
    if (e >= E) return;
    int s = __ldg(&src[e]);
    int d = __ldg(&dst[e]);
    float4 v = *(const float4*)&hsrc[(size_t)s * 64 + lane * 4];
    float* p = &agg[(size_t)d * 64 + lane * 4];
    asm volatile("red.global.add.v4.f32 [%0], {%1,%2,%3,%4};"
                 :: "l"(p), "f"(v.x), "f"(v.y), "f"(v.z), "f"(v.w) : "memory");
    if (lane == 0) atomicAdd(&cnt[d], 1);
}

// ---------------- launch ----------------
extern "C" void kernel_launch(void* const* d_in, const int* in_sizes, int n_in,
                              void* d_out, int out_size)
{
    const float* x      = (const float*)d_in[0];
    const float* W_src1 = (const float*)d_in[1];
    const float* W_dst1 = (const float*)d_in[2];
    const float* W_out1 = (const float*)d_in[3];
    const float* b1     = (const float*)d_in[4];
    const float* W_src2 = (const float*)d_in[5];
    const float* W_dst2 = (const float*)d_in[6];
    const float* W_out2 = (const float*)d_in[7];
    const float* b2     = (const float*)d_in[8];
    const int*   src1   = (const int*)d_in[9];
    const int*   dst1   = (const int*)d_in[10];
    const int*   src2   = (const int*)d_in[11];
    const int*   dst2   = (const int*)d_in[12];
    const int E1 = in_sizes[9];
    const int E2 = in_sizes[11];

    float *hsrc1, *agg1, *z, *h, *hsrc2, *agg2;
    int *cnt1, *cnt2;
    cudaGetSymbolAddress((void**)&hsrc1, g_hsrc1);
    cudaGetSymbolAddress((void**)&agg1,  g_agg1);
    cudaGetSymbolAddress((void**)&cnt1,  g_cnt1);
    cudaGetSymbolAddress((void**)&z,     g_z);
    cudaGetSymbolAddress((void**)&h,     g_h);
    cudaGetSymbolAddress((void**)&hsrc2, g_hsrc2);
    cudaGetSymbolAddress((void**)&agg2,  g_agg2);
    cudaGetSymbolAddress((void**)&cnt2,  g_cnt2);

    float* out = (float*)d_out;

    // zero accumulators
    zero_f<<<(C_N1 * C_RANK + 255) / 256, 256>>>(agg1, C_N1 * C_RANK);
    zero_i<<<(C_N1 + 255) / 256, 256>>>(cnt1, C_N1);
    zero_f<<<(C_N2 * C_RANK + 255) / 256, 256>>>(agg2, C_N2 * C_RANK);
    zero_i<<<(C_N2 + 255) / 256, 256>>>(cnt2, C_N2);

    // ---- layer 1 ----
    // h_src1 = x @ W_src1  [200000,128]x[128,64]
    {
        dim3 grid((C_N0 + 63) / 64, 1);
        gemm_kernel<false, false, false><<<grid, 256>>>(x, W_src1, hsrc1,
            nullptr, nullptr, nullptr, C_N0, C_INF, C_RANK);
    }
    // scatter-mean over edges 1
    edge_scatter<<<((size_t)E1 * 16 + 255) / 256, 256>>>(hsrc1, src1, dst1, agg1, cnt1, E1);
    // z1 = (x[:N1] @ W_dst1) * agg1/cnt1
    {
        dim3 grid((C_N1 + 63) / 64, 1);
        gemm_kernel<true, false, false><<<grid, 256>>>(x, W_dst1, z,
            agg1, cnt1, nullptr, C_N1, C_INF, C_RANK);
    }
    // h = relu(z1 @ W_out1 + b1)  [50000,64]x[64,128]
    {
        dim3 grid((C_N1 + 63) / 64, C_HID / 64);
        gemm_kernel<false, true, true><<<grid, 256>>>(z, W_out1, h,
            nullptr, nullptr, b1, C_N1, C_RANK, C_HID);
    }

    // ---- layer 2 ----
    // h_src2 = h @ W_src2  [50000,128]x[128,64]
    {
        dim3 grid((C_N1 + 63) / 64, 1);
        gemm_kernel<false, false, false><<<grid, 256>>>(h, W_src2, hsrc2,
            nullptr, nullptr, nullptr, C_N1, C_HID, C_RANK);
    }
    edge_scatter<<<((size_t)E2 * 16 + 255) / 256, 256>>>(hsrc2, src2, dst2, agg2, cnt2, E2);
    // z2 = (h[:N2] @ W_dst2) * agg2/cnt2
    {
        dim3 grid((C_N2 + 63) / 64, 1);
        gemm_kernel<true, false, false><<<grid, 256>>>(h, W_dst2, z,
            agg2, cnt2, nullptr, C_N2, C_HID, C_RANK);
    }
    // out = z2 @ W_out2 + b2  [10000,64]x[64,64]
    {
        dim3 grid((C_N2 + 63) / 64, 1);
        gemm_kernel<false, true, false><<<grid, 256>>>(z, W_out2, out,
            nullptr, nullptr, b2, C_N2, C_RANK, C_OUTC);
    }
}

// round 3
// speedup vs baseline: 1.3845x; 1.3845x over previous
#include <cuda_runtime.h>
#include <cstdint>

// Problem constants (from reference)
#define C_N0 200000
#define C_N1 50000
#define C_N2 10000
#define C_INF 128
#define C_HID 128
#define C_RANK 64
#define C_OUTC 64
#define C_E1 800000
#define C_E2 160000

// ---------------- scratch (device globals; no allocation) ----------------
__device__ int   g_cnt1 [C_N1];
__device__ int   g_off1 [C_N1];
__device__ int   g_pos1 [C_N1];
__device__ int   g_adj1 [C_E1];
__device__ float g_aggx1[(size_t)C_N1 * C_INF];    // 25.6 MB: mean of x over edges
__device__ float g_z    [(size_t)C_N1 * C_RANK];   // z1 (reused for z2)
__device__ float g_h    [(size_t)C_N1 * C_HID];    // 25.6 MB
__device__ int   g_cnt2 [C_N2];
__device__ int   g_off2 [C_N2];
__device__ int   g_pos2 [C_N2];
__device__ int   g_adj2 [C_E2];
__device__ float g_aggh2[(size_t)C_N2 * C_HID];
__device__ int   g_blk  [256];                     // block sums for scan

// ---------------- small utility kernels ----------------
__global__ void zero_i2(int* __restrict__ a, int* __restrict__ b, int n) {
    int i = blockIdx.x * blockDim.x + threadIdx.x;
    if (i < n) { a[i] = 0; b[i] = 0; }
}

// histogram of dst
__global__ void hist_kernel(const int* __restrict__ dst, int* __restrict__ cnt, int E) {
    int e = blockIdx.x * blockDim.x + threadIdx.x;
    if (e < E) atomicAdd(&cnt[dst[e]], 1);
}

// hierarchical exclusive scan: phase 1 (1024 items / block of 256 threads)
__global__ void scan_partial(const int* __restrict__ cnt, int* __restrict__ off,
                             int* __restrict__ blksum, int n) {
    __shared__ int s[256];
    int b = blockIdx.x;
    int base = b * 1024 + threadIdx.x * 4;
    int v0 = (base + 0 < n) ? cnt[base + 0] : 0;
    int v1 = (base + 1 < n) ? cnt[base + 1] : 0;
    int v2 = (base + 2 < n) ? cnt[base + 2] : 0;
    int v3 = (base + 3 < n) ? cnt[base + 3] : 0;
    int sum = v0 + v1 + v2 + v3;
    s[threadIdx.x] = sum;
    __syncthreads();
    // Hillis-Steele inclusive scan over 256 thread sums
    #pragma unroll
    for (int d = 1; d < 256; d <<= 1) {
        int t = (threadIdx.x >= d) ? s[threadIdx.x - d] : 0;
        __syncthreads();
        s[threadIdx.x] += t;
        __syncthreads();
    }
    int run = s[threadIdx.x] - sum;   // exclusive
    if (base + 0 < n) { off[base + 0] = run; run += v0; }
    if (base + 1 < n) { off[base + 1] = run; run += v1; }
    if (base + 2 < n) { off[base + 2] = run; run += v2; }
    if (base + 3 < n) { off[base + 3] = run; }
    if (threadIdx.x == 255) blksum[b] = s[255];
}

// phase 2: exclusive scan of block sums (nb <= 64) — single thread, trivial
__global__ void scan_aux(int* __restrict__ blksum, int nb) {
    if (threadIdx.x == 0 && blockIdx.x == 0) {
        int run = 0;
        for (int i = 0; i < nb; i++) { int t = blksum[i]; blksum[i] = run; run += t; }
    }
}

// phase 3: add block offsets
__global__ void scan_add(int* __restrict__ off, const int* __restrict__ blksum, int n) {
    int i = blockIdx.x * blockDim.x + threadIdx.x;
    if (i < n) off[i] += blksum[i >> 10];
}

// fill adjacency: adj[off[d] + pos[d]++] = src[e]
__global__ void fill_adj(const int* __restrict__ src, const int* __restrict__ dst,
                         const int* __restrict__ off, int* __restrict__ pos,
                         int* __restrict__ adj, int E) {
    int e = blockIdx.x * blockDim.x + threadIdx.x;
    if (e < E) {
        int d = dst[e];
        int p = atomicAdd(&pos[d], 1);
        adj[off[d] + p] = src[e];
    }
}

// gather-mean over 128-dim features: one warp per dst row.
// out[d] = mean_{j in adj[d]} feat[adj_j]   (0 if no edges)
__global__ void gather_mean128(const float* __restrict__ feat,
                               const int* __restrict__ adj,
                               const int* __restrict__ off,
                               const int* __restrict__ cnt,
                               float* __restrict__ out, int Ndst) {
    int warp = (blockIdx.x * blockDim.x + threadIdx.x) >> 5;
    int lane = threadIdx.x & 31;
    if (warp >= Ndst) return;
    int s0 = off[warp];
    int c  = cnt[warp];
    float4 acc = make_float4(0.f, 0.f, 0.f, 0.f);
    int j = 0;
    for (; j + 1 < c; j += 2) {                  // 2-deep MLP
        int sA = __ldg(&adj[s0 + j]);
        int sB = __ldg(&adj[s0 + j + 1]);
        float4 a = *(const float4*)&feat[(size_t)sA * 128 + lane * 4];
        float4 b = *(const float4*)&feat[(size_t)sB * 128 + lane * 4];
        acc.x += a.x + b.x; acc.y += a.y + b.y;
        acc.z += a.z + b.z; acc.w += a.w + b.w;
    }
    if (j < c) {
        int sA = __ldg(&adj[s0 + j]);
        float4 a = *(const float4*)&feat[(size_t)sA * 128 + lane * 4];
        acc.x += a.x; acc.y += a.y; acc.z += a.z; acc.w += a.w;
    }
    float sc = 1.0f / fmaxf((float)c, 1.0f);
    float4 v = make_float4(acc.x * sc, acc.y * sc, acc.z * sc, acc.w * sc);
    *(float4*)&out[(size_t)warp * 128 + lane * 4] = v;
}

// ---------------- fused dual GEMM:  Z = (Aagg @ Wa) * (Ax @ Wb) ----------
// K = 128, N = 64 fixed. Tile 64 rows, 256 threads, 4x4 per thread per stream.
__global__ void dual_gemm_kernel(const float* __restrict__ Aagg,
                                 const float* __restrict__ Ax,
                                 const float* __restrict__ Wa,
                                 const float* __restrict__ Wb,
                                 float* __restrict__ Z, int M)
{
    __shared__ float Bs[2 * 128 * 64];   // Wa panel then Wb panel (64 KB)
    __shared__ float As[16][68];

    const int row0 = blockIdx.x * 64;
    const int t  = threadIdx.x;
    const int tx = t & 15;
    const int ty = t >> 4;

    // load both weight panels (each [128,64], row-major, N==64 contiguous)
    for (int i = t; i < 128 * 64; i += 256) {
        Bs[i]             = Wa[i];
        Bs[128 * 64 + i]  = Wb[i];
    }

    float accA[4][4] = {};
    float accB[4][4] = {};

    const int ks    = t & 15;
    const int rbase = t >> 4;

    __syncthreads();

    for (int kk = 0; kk < 128; kk += 16) {
        // ---- stream A: Aagg ----
        #pragma unroll
        for (int i = 0; i < 4; i++) {
            int r = rbase + i * 16;
            int gr = row0 + r;
            As[ks][r] = (gr < M) ? Aagg[(size_t)gr * 128 + kk + ks] : 0.0f;
        }
        __syncthreads();
        #pragma unroll
        for (int k = 0; k < 16; k++) {
            float4 a = *(const float4*)&As[k][ty * 4];
            float4 b = *(const float4*)&Bs[(kk + k) * 64 + tx * 4];
            accA[0][0] += a.x * b.x; accA[0][1] += a.x * b.y; accA[0][2] += a.x * b.z; accA[0][3] += a.x * b.w;
            accA[1][0] += a.y * b.x; accA[1][1] += a.y * b.y; accA[1][2] += a.y * b.z; accA[1][3] += a.y * b.w;
            accA[2][0] += a.z * b.x; accA[2][1] += a.z * b.y; accA[2][2] += a.z * b.z; accA[2][3] += a.z * b.w;
            accA[3][0] += a.w * b.x; accA[3][1] += a.w * b.y; accA[3][2] += a.w * b.z; accA[3][3] += a.w * b.w;
        }
        __syncthreads();
        // ---- stream B: Ax ----
        #pragma unroll
        for (int i = 0; i < 4; i++) {
            int r = rbase + i * 16;
            int gr = row0 + r;
            As[ks][r] = (gr < M) ? Ax[(size_t)gr * 128 + kk + ks] : 0.0f;
        }
        __syncthreads();
        #pragma unroll
        for (int k = 0; k < 16; k++) {
            float4 a = *(const float4*)&As[k][ty * 4];
            float4 b = *(const float4*)&Bs[128 * 64 + (kk + k) * 64 + tx * 4];
            accB[0][0] += a.x * b.x; accB[0][1] += a.x * b.y; accB[0][2] += a.x * b.z; accB[0][3] += a.x * b.w;
            accB[1][0] += a.y * b.x; accB[1][1] += a.y * b.y; accB[1][2] += a.y * b.z; accB[1][3] += a.y * b.w;
            accB[2][0] += a.z * b.x; accB[2][1] += a.z * b.y; accB[2][2] += a.z * b.z; accB[2][3] += a.z * b.w;
            accB[3][0] += a.w * b.x; accB[3][1] += a.w * b.y; accB[3][2] += a.w * b.z; accB[3][3] += a.w * b.w;
        }
        __syncthreads();
    }

    #pragma unroll
    for (int i = 0; i < 4; i++) {
        int r = row0 + ty * 4 + i;
        if (r >= M) continue;
        float4 v = make_float4(accA[i][0] * accB[i][0], accA[i][1] * accB[i][1],
                               accA[i][2] * accB[i][2], accA[i][3] * accB[i][3]);
        *(float4*)&Z[(size_t)r * 64 + tx * 4] = v;
    }
}

// ---------------- tiled GEMM: C[M,N] = A[M,K] @ B[K,N] (+ epilogue) ------
template <bool BIAS, bool RELU>
__global__ void gemm_kernel(const float* __restrict__ A,
                            const float* __restrict__ B,
                            float* __restrict__ C,
                            const float* __restrict__ bias,
                            int M, int K, int N)
{
    __shared__ float Bs[128 * 64];
    __shared__ float As[16][68];

    const int row0 = blockIdx.x * 64;
    const int col0 = blockIdx.y * 64;
    const int t  = threadIdx.x;
    const int tx = t & 15;
    const int ty = t >> 4;

    for (int i = t; i < K * 64; i += 256) {
        int k = i >> 6, n = i & 63;
        Bs[i] = B[(size_t)k * N + col0 + n];
    }

    float acc[4][4] = {};
    const int ks    = t & 15;
    const int rbase = t >> 4;

    __syncthreads();

    for (int kk = 0; kk < K; kk += 16) {
        #pragma unroll
        for (int i = 0; i < 4; i++) {
            int r = rbase + i * 16;
            int gr = row0 + r;
            As[ks][r] = (gr < M) ? A[(size_t)gr * K + kk + ks] : 0.0f;
        }
        __syncthreads();
        #pragma unroll
        for (int k = 0; k < 16; k++) {
            float4 a = *(const float4*)&As[k][ty * 4];
            float4 b = *(const float4*)&Bs[(kk + k) * 64 + tx * 4];
            acc[0][0] += a.x * b.x; acc[0][1] += a.x * b.y; acc[0][2] += a.x * b.z; acc[0][3] += a.x * b.w;
            acc[1][0] += a.y * b.x; acc[1][1] += a.y * b.y; acc[1][2] += a.y * b.z; acc[1][3] += a.y * b.w;
            acc[2][0] += a.z * b.x; acc[2][1] += a.z * b.y; acc[2][2] += a.z * b.z; acc[2][3] += a.z * b.w;
            acc[3][0] += a.w * b.x; acc[3][1] += a.w * b.y; acc[3][2] += a.w * b.z; acc[3][3] += a.w * b.w;
        }
        __syncthreads();
    }

    #pragma unroll
    for (int i = 0; i < 4; i++) {
        int r = row0 + ty * 4 + i;
        if (r >= M) continue;
        float4 v = make_float4(acc[i][0], acc[i][1], acc[i][2], acc[i][3]);
        if (BIAS) {
            const float4 bb = *(const float4*)&bias[col0 + tx * 4];
            v.x += bb.x; v.y += bb.y; v.z += bb.z; v.w += bb.w;
        }
        if (RELU) {
            v.x = fmaxf(v.x, 0.0f); v.y = fmaxf(v.y, 0.0f);
            v.z = fmaxf(v.z, 0.0f); v.w = fmaxf(v.w, 0.0f);
        }
        *(float4*)&C[(size_t)r * N + col0 + tx * 4] = v;
    }
}

// ---------------- launch ----------------
extern "C" void kernel_launch(void* const* d_in, const int* in_sizes, int n_in,
                              void* d_out, int out_size)
{
    const float* x      = (const float*)d_in[0];
    const float* W_src1 = (const float*)d_in[1];
    const float* W_dst1 = (const float*)d_in[2];
    const float* W_out1 = (const float*)d_in[3];
    const float* b1     = (const float*)d_in[4];
    const float* W_src2 = (const float*)d_in[5];
    const float* W_dst2 = (const float*)d_in[6];
    const float* W_out2 = (const float*)d_in[7];
    const float* b2     = (const float*)d_in[8];
    const int*   src1   = (const int*)d_in[9];
    const int*   dst1   = (const int*)d_in[10];
    const int*   src2   = (const int*)d_in[11];
    const int*   dst2   = (const int*)d_in[12];
    const int E1 = in_sizes[9];
    const int E2 = in_sizes[11];

    int *cnt1, *off1, *pos1, *adj1, *cnt2, *off2, *pos2, *adj2, *blk;
    float *aggx1, *z, *h, *aggh2;
    cudaGetSymbolAddress((void**)&cnt1,  g_cnt1);
    cudaGetSymbolAddress((void**)&off1,  g_off1);
    cudaGetSymbolAddress((void**)&pos1,  g_pos1);
    cudaGetSymbolAddress((void**)&adj1,  g_adj1);
    cudaGetSymbolAddress((void**)&aggx1, g_aggx1);
    cudaGetSymbolAddress((void**)&z,     g_z);
    cudaGetSymbolAddress((void**)&h,     g_h);
    cudaGetSymbolAddress((void**)&cnt2,  g_cnt2);
    cudaGetSymbolAddress((void**)&off2,  g_off2);
    cudaGetSymbolAddress((void**)&pos2,  g_pos2);
    cudaGetSymbolAddress((void**)&adj2,  g_adj2);
    cudaGetSymbolAddress((void**)&aggh2, g_aggh2);
    cudaGetSymbolAddress((void**)&blk,   g_blk);

    float* out = (float*)d_out;

    // ======== layer 1 CSR build ========
    zero_i2<<<(C_N1 + 255) / 256, 256>>>(cnt1, pos1, C_N1);
    hist_kernel<<<(E1 + 255) / 256, 256>>>(dst1, cnt1, E1);
    {
        int nb = (C_N1 + 1023) / 1024;   // 49
        scan_partial<<<nb, 256>>>(cnt1, off1, blk, C_N1);
        scan_aux<<<1, 32>>>(blk, nb);
        scan_add<<<(C_N1 + 255) / 256, 256>>>(off1, blk, C_N1);
    }
    fill_adj<<<(E1 + 255) / 256, 256>>>(src1, dst1, off1, pos1, adj1, E1);

    // aggx1 = segment_mean(x over edges1)   [N1,128]
    gather_mean128<<<(C_N1 * 32 + 255) / 256, 256>>>(x, adj1, off1, cnt1, aggx1, C_N1);

    // z1 = (aggx1 @ W_src1) * (x[:N1] @ W_dst1)
    dual_gemm_kernel<<<(C_N1 + 63) / 64, 256>>>(aggx1, x, W_src1, W_dst1, z, C_N1);

    // h = relu(z1 @ W_out1 + b1)   [50000,64]x[64,128]
    {
        dim3 grid((C_N1 + 63) / 64, C_HID / 64);
        gemm_kernel<true, true><<<grid, 256>>>(z, W_out1, h, b1, C_N1, C_RANK, C_HID);
    }

    // ======== layer 2 CSR build ========
    zero_i2<<<(C_N2 + 255) / 256, 256>>>(cnt2, pos2, C_N2);
    hist_kernel<<<(E2 + 255) / 256, 256>>>(dst2, cnt2, E2);
    {
        int nb = (C_N2 + 1023) / 1024;   // 10
        scan_partial<<<nb, 256>>>(cnt2, off2, blk, C_N2);
        scan_aux<<<1, 32>>>(blk, nb);
        scan_add<<<(C_N2 + 255) / 256, 256>>>(off2, blk, C_N2);
    }
    fill_adj<<<(E2 + 255) / 256, 256>>>(src2, dst2, off2, pos2, adj2, E2);

    // aggh2 = segment_mean(h over edges2)   [N2,128]
    gather_mean128<<<(C_N2 * 32 + 255) / 256, 256>>>(h, adj2, off2, cnt2, aggh2, C_N2);

    // z2 = (aggh2 @ W_src2) * (h[:N2] @ W_dst2)
    dual_gemm_kernel<<<(C_N2 + 63) / 64, 256>>>(aggh2, h, W_src2, W_dst2, z, C_N2);

    // out = z2 @ W_out2 + b2   [10000,64]x[64,64]
    {
        dim3 grid((C_N2 + 63) / 64, 1);
        gemm_kernel<true, false><<<grid, 256>>>(z, W_out2, out, b2, C_N2, C_RANK, C_OUTC);
    }
}

// round 5
// speedup vs baseline: 1.7596x; 1.2709x over previous
#include <cuda_runtime.h>
#include <cstdint>

// Problem constants (from reference)
#define C_N0 200000
#define C_N1 50000
#define C_N2 10000
#define C_INF 128
#define C_HID 128
#define C_RANK 64
#define C_OUTC 64
#define C_E1 800000
#define C_E2 160000

// ---------------- scratch (device globals; no allocation) ----------------
__device__ int   g_cnt1 [C_N1];
__device__ int   g_off1 [C_N1];
__device__ int   g_pos1 [C_N1];
__device__ int   g_adj1 [C_E1];
__device__ float g_aggx1[(size_t)C_N1 * C_INF];
__device__ float g_z    [(size_t)C_N1 * C_RANK];
__device__ float g_h    [(size_t)C_N1 * C_HID];
__device__ int   g_cnt2 [C_N2];
__device__ int   g_off2 [C_N2];
__device__ int   g_pos2 [C_N2];
__device__ int   g_adj2 [C_E2];
__device__ float g_aggh2[(size_t)C_N2 * C_HID];
__device__ int   g_blk  [256];

// fragment-major tf32 weight panels: [kstep][ntile][lane]{b0,b1}
__device__ float g_fS1[128 * 64];
__device__ float g_fD1[128 * 64];
__device__ float g_fO1[64 * 128];
__device__ float g_fS2[128 * 64];
__device__ float g_fD2[128 * 64];
__device__ float g_fO2[64 * 64];

// ---------------- helpers ----------------
__device__ __forceinline__ uint32_t f2tf32(float f) {
    uint32_t r;
    asm("cvt.rna.tf32.f32 %0, %1;" : "=r"(r) : "f"(f));
    return r;
}
__device__ __forceinline__ void mma_tf32(float* c, uint32_t a0, uint32_t a1,
                                         uint32_t a2, uint32_t a3,
                                         uint32_t b0, uint32_t b1) {
    asm volatile(
        "mma.sync.aligned.m16n8k8.row.col.f32.tf32.tf32.f32 "
        "{%0,%1,%2,%3}, {%4,%5,%6,%7}, {%8,%9}, {%0,%1,%2,%3};"
        : "+f"(c[0]), "+f"(c[1]), "+f"(c[2]), "+f"(c[3])
        : "r"(a0), "r"(a1), "r"(a2), "r"(a3), "r"(b0), "r"(b1));
}

// ---------------- weight prep: W[K,N] row-major -> fragment-major tf32 ----
// frag idx = ((kk*(N/8)+nt)*32 + lane)*2 + p ; element = W[kk*8+(lane&3)+p*4][nt*8+(lane>>2)]
__global__ void prep_frags(const float* __restrict__ Ws1, const float* __restrict__ Wd1,
                           const float* __restrict__ Wo1, const float* __restrict__ Ws2,
                           const float* __restrict__ Wd2, const float* __restrict__ Wo2,
                           float* __restrict__ Fs1, float* __restrict__ Fd1,
                           float* __restrict__ Fo1, float* __restrict__ Fs2,
                           float* __restrict__ Fd2, float* __restrict__ Fo2)
{
    int i = blockIdx.x * 256 + threadIdx.x;
    const float* W; float* F; int N, idx;
    if      (i < 8192)  { W = Ws1; F = Fs1; N = 64;  idx = i; }
    else if (i < 16384) { W = Wd1; F = Fd1; N = 64;  idx = i - 8192; }
    else if (i < 24576) { W = Wo1; F = Fo1; N = 128; idx = i - 16384; }
    else if (i < 32768) { W = Ws2; F = Fs2; N = 64;  idx = i - 24576; }
    else if (i < 40960) { W = Wd2; F = Fd2; N = 64;  idx = i - 32768; }
    else if (i < 45056) { W = Wo2; F = Fo2; N = 64;  idx = i - 40960; }
    else return;
    int p    = idx & 1;
    int lane = (idx >> 1) & 31;
    int t    = idx >> 6;
    int NT   = N / 8;
    int nt   = t % NT;
    int kk   = t / NT;
    int k = kk * 8 + (lane & 3) + p * 4;
    int n = nt * 8 + (lane >> 2);
    uint32_t v = f2tf32(W[k * N + n]);
    F[idx] = __uint_as_float(v);
}

// ---------------- warp-MMA tf32 GEMM -------------------------------------
// MODE 0: C[M,64]  = (A1@W1) * (A2@W2)    K=128, N=64   (dual stream)
// MODE 1: C[M,128] = relu(A1@W1 + bias)   K=64,  N=128
// MODE 2: C[M,64]  = A1@W1 + bias         K=64,  N=64
// CTA: 256 threads = 8 warps, 128 rows (16 rows/warp). A staged in smem
// padded KP=K+4 (conflict-free fragment LDS); B panels fragment-major in smem.
template <int K, int N, int MODE>
__global__ void __launch_bounds__(256, 1)
mma_gemm(const float* __restrict__ A1, const float* __restrict__ A2,
         const float* __restrict__ F1, const float* __restrict__ F2,
         const float* __restrict__ bias, float* __restrict__ C, int M)
{
    extern __shared__ float smem[];
    constexpr int KP = K + 4;
    constexpr int NT = N / 8;
    constexpr int KS = K / 8;

    float* As  = smem;                 // 128 * KP
    float* Bf1 = smem + 128 * KP;      // K*N floats
    float* Bf2 = Bf1 + K * N;          // only MODE 0

    const int tid  = threadIdx.x;
    const int wid  = tid >> 5;
    const int lane = tid & 31;
    const int g    = lane >> 2;
    const int tig  = lane & 3;
    const int row0 = blockIdx.x * 128;

    // copy B fragment panels (linear float4)
    {
        const float4* s1 = (const float4*)F1;
        float4* d1 = (float4*)Bf1;
        #pragma unroll 4
        for (int i = tid; i < K * N / 4; i += 256) d1[i] = s1[i];
        if (MODE == 0) {
            const float4* s2 = (const float4*)F2;
            float4* d2 = (float4*)Bf2;
            #pragma unroll 4
            for (int i = tid; i < K * N / 4; i += 256) d2[i] = s2[i];
        }
    }

    // stage A1 (tf32-converted, padded)
    #pragma unroll 2
    for (int i = tid; i < 128 * (K / 4); i += 256) {
        int r = i / (K / 4);
        int c = (i % (K / 4)) * 4;
        int gr = row0 + r;
        float4 v = make_float4(0.f, 0.f, 0.f, 0.f);
        if (gr < M) v = *(const float4*)&A1[(size_t)gr * K + c];
        uint4 t;
        t.x = f2tf32(v.x); t.y = f2tf32(v.y); t.z = f2tf32(v.z); t.w = f2tf32(v.w);
        *(uint4*)&As[r * KP + c] = t;
    }
    __syncthreads();

    float accA[NT][4];
    #pragma unroll
    for (int nt = 0; nt < NT; nt++)
        { accA[nt][0] = accA[nt][1] = accA[nt][2] = accA[nt][3] = 0.f; }

    const float* abase = &As[(wid * 16 + g) * KP + tig];

    #pragma unroll
    for (int kk = 0; kk < KS; kk++) {
        uint32_t a0 = __float_as_uint(abase[kk * 8 + 0]);
        uint32_t a2 = __float_as_uint(abase[kk * 8 + 4]);
        uint32_t a1 = __float_as_uint(abase[kk * 8 + 8 * KP]);
        uint32_t a3 = __float_as_uint(abase[kk * 8 + 8 * KP + 4]);
        const float2* bf = (const float2*)Bf1 + (size_t)(kk * NT) * 32 + lane;
        #pragma unroll
        for (int nt = 0; nt < NT; nt++) {
            float2 b = bf[nt * 32];
            mma_tf32(accA[nt], a0, a1, a2, a3,
                     __float_as_uint(b.x), __float_as_uint(b.y));
        }
    }

    float accB[MODE == 0 ? NT : 1][4];
    if (MODE == 0) {
        __syncthreads();
        // stage A2 into same buffer
        #pragma unroll 2
        for (int i = tid; i < 128 * (K / 4); i += 256) {
            int r = i / (K / 4);
            int c = (i % (K / 4)) * 4;
            int gr = row0 + r;
            float4 v = make_float4(0.f, 0.f, 0.f, 0.f);
            if (gr < M) v = *(const float4*)&A2[(size_t)gr * K + c];
            uint4 t;
            t.x = f2tf32(v.x); t.y = f2tf32(v.y); t.z = f2tf32(v.z); t.w = f2tf32(v.w);
            *(uint4*)&As[r * KP + c] = t;
        }
        __syncthreads();
        #pragma unroll
        for (int nt = 0; nt < NT; nt++)
            { accB[nt][0] = accB[nt][1] = accB[nt][2] = accB[nt][3] = 0.f; }
        #pragma unroll
        for (int kk = 0; kk < KS; kk++) {
            uint32_t a0 = __float_as_uint(abase[kk * 8 + 0]);
            uint32_t a2 = __float_as_uint(abase[kk * 8 + 4]);
            uint32_t a1 = __float_as_uint(abase[kk * 8 + 8 * KP]);
            uint32_t a3 = __float_as_uint(abase[kk * 8 + 8 * KP + 4]);
            const float2* bf = (const float2*)Bf2 + (size_t)(kk * NT) * 32 + lane;
            #pragma unroll
            for (int nt = 0; nt < NT; nt++) {
                float2 b = bf[nt * 32];
                mma_tf32(accB[nt], a0, a1, a2, a3,
                         __float_as_uint(b.x), __float_as_uint(b.y));
            }
        }
    }

    // epilogue
    const int r0 = row0 + wid * 16 + g;
    const int r1 = r0 + 8;
    const int cb = 2 * tig;
    #pragma unroll
    for (int nt = 0; nt < NT; nt++) {
        int col = nt * 8 + cb;
        if (MODE == 0) {
            if (r0 < M) {
                float2 v = make_float2(accA[nt][0] * accB[nt][0],
                                       accA[nt][1] * accB[nt][1]);
                *(float2*)&C[(size_t)r0 * N + col] = v;
            }
            if (r1 < M) {
                float2 v = make_float2(accA[nt][2] * accB[nt][2],
                                       accA[nt][3] * accB[nt][3]);
                *(float2*)&C[(size_t)r1 * N + col] = v;
            }
        } else {
            float2 bb = *(const float2*)&bias[col];
            float2 v0 = make_float2(accA[nt][0] + bb.x, accA[nt][1] + bb.y);
            float2 v1 = make_float2(accA[nt][2] + bb.x, accA[nt][3] + bb.y);
            if (MODE == 1) {
                v0.x = fmaxf(v0.x, 0.f); v0.y = fmaxf(v0.y, 0.f);
                v1.x = fmaxf(v1.x, 0.f); v1.y = fmaxf(v1.y, 0.f);
            }
            if (r0 < M) *(float2*)&C[(size_t)r0 * N + col] = v0;
            if (r1 < M) *(float2*)&C[(size_t)r1 * N + col] = v1;
        }
    }
}

// ---------------- CSR build + gather ----------------
__global__ void zero_all(int* __restrict__ c1, int* __restrict__ p1,
                         int* __restrict__ c2, int* __restrict__ p2) {
    int i = blockIdx.x * blockDim.x + threadIdx.x;
    if (i < C_N1) { c1[i] = 0; p1[i] = 0; }
    if (i < C_N2) { c2[i] = 0; p2[i] = 0; }
}

__global__ void hist_kernel(const int* __restrict__ dst, int* __restrict__ cnt, int E) {
    int e = blockIdx.x * blockDim.x + threadIdx.x;
    if (e < E) atomicAdd(&cnt[dst[e]], 1);
}

__global__ void scan_partial(const int* __restrict__ cnt, int* __restrict__ off,
                             int* __restrict__ blksum, int n) {
    __shared__ int s[256];
    int b = blockIdx.x;
    int base = b * 1024 + threadIdx.x * 4;
    int v0 = (base + 0 < n) ? cnt[base + 0] : 0;
    int v1 = (base + 1 < n) ? cnt[base + 1] : 0;
    int v2 = (base + 2 < n) ? cnt[base + 2] : 0;
    int v3 = (base + 3 < n) ? cnt[base + 3] : 0;
    int sum = v0 + v1 + v2 + v3;
    s[threadIdx.x] = sum;
    __syncthreads();
    #pragma unroll
    for (int d = 1; d < 256; d <<= 1) {
        int t = (threadIdx.x >= d) ? s[threadIdx.x - d] : 0;
        __syncthreads();
        s[threadIdx.x] += t;
        __syncthreads();
    }
    int run = s[threadIdx.x] - sum;
    if (base + 0 < n) { off[base + 0] = run; run += v0; }
    if (base + 1 < n) { off[base + 1] = run; run += v1; }
    if (base + 2 < n) { off[base + 2] = run; run += v2; }
    if (base + 3 < n) { off[base + 3] = run; }
    if (threadIdx.x == 255) blksum[b] = s[255];
}

__global__ void scan_aux(int* __restrict__ blk, int nb) {
    __shared__ int s[64];
    int i = threadIdx.x;
    int v = (i < nb) ? blk[i] : 0;
    s[i] = v;
    __syncthreads();
    #pragma unroll
    for (int d = 1; d < 64; d <<= 1) {
        int t = (i >= d) ? s[i - d] : 0;
        __syncthreads();
        s[i] += t;
        __syncthreads();
    }
    if (i < nb) blk[i] = s[i] - v;
}

__global__ void scan_add(int* __restrict__ off, const int* __restrict__ blksum, int n) {
    int i = blockIdx.x * blockDim.x + threadIdx.x;
    if (i < n) off[i] += blksum[i >> 10];
}

__global__ void fill_adj(const int* __restrict__ src, const int* __restrict__ dst,
                         const int* __restrict__ off, int* __restrict__ pos,
                         int* __restrict__ adj, int E) {
    int e = blockIdx.x * blockDim.x + threadIdx.x;
    if (e < E) {
        int d = dst[e];
        int p = atomicAdd(&pos[d], 1);
        adj[off[d] + p] = src[e];
    }
}

__global__ void gather_mean128(const float* __restrict__ feat,
                               const int* __restrict__ adj,
                               const int* __restrict__ off,
                               const int* __restrict__ cnt,
                               float* __restrict__ out, int Ndst) {
    int warp = (blockIdx.x * blockDim.x + threadIdx.x) >> 5;
    int lane = threadIdx.x & 31;
    if (warp >= Ndst) return;
    int s0 = off[warp];
    int c  = cnt[warp];
    float4 acc = make_float4(0.f, 0.f, 0.f, 0.f);
    int j = 0;
    for (; j + 1 < c; j += 2) {
        int sA = __ldg(&adj[s0 + j]);
        int sB = __ldg(&adj[s0 + j + 1]);
        float4 a = *(const float4*)&feat[(size_t)sA * 128 + lane * 4];
        float4 b = *(const float4*)&feat[(size_t)sB * 128 + lane * 4];
        acc.x += a.x + b.x; acc.y += a.y + b.y;
        acc.z += a.z + b.z; acc.w += a.w + b.w;
    }
    if (j < c) {
        int sA = __ldg(&adj[s0 + j]);
        float4 a = *(const float4*)&feat[(size_t)sA * 128 + lane * 4];
        acc.x += a.x; acc.y += a.y; acc.z += a.z; acc.w += a.w;
    }
    float sc = 1.0f / fmaxf((float)c, 1.0f);
    float4 v = make_float4(acc.x * sc, acc.y * sc, acc.z * sc, acc.w * sc);
    *(float4*)&out[(size_t)warp * 128 + lane * 4] = v;
}

// ---------------- launch ----------------
extern "C" void kernel_launch(void* const* d_in, const int* in_sizes, int n_in,
                              void* d_out, int out_size)
{
    const float* x      = (const float*)d_in[0];
    const float* W_src1 = (const float*)d_in[1];
    const float* W_dst1 = (const float*)d_in[2];
    const float* W_out1 = (const float*)d_in[3];
    const float* b1     = (const float*)d_in[4];
    const float* W_src2 = (const float*)d_in[5];
    const float* W_dst2 = (const float*)d_in[6];
    const float* W_out2 = (const float*)d_in[7];
    const float* b2     = (const float*)d_in[8];
    const int*   src1   = (const int*)d_in[9];
    const int*   dst1   = (const int*)d_in[10];
    const int*   src2   = (const int*)d_in[11];
    const int*   dst2   = (const int*)d_in[12];
    const int E1 = in_sizes[9];
    const int E2 = in_sizes[11];

    int *cnt1, *off1, *pos1, *adj1, *cnt2, *off2, *pos2, *adj2, *blk;
    float *aggx1, *z, *h, *aggh2;
    float *fS1, *fD1, *fO1, *fS2, *fD2, *fO2;
    cudaGetSymbolAddress((void**)&cnt1,  g_cnt1);
    cudaGetSymbolAddress((void**)&off1,  g_off1);
    cudaGetSymbolAddress((void**)&pos1,  g_pos1);
    cudaGetSymbolAddress((void**)&adj1,  g_adj1);
    cudaGetSymbolAddress((void**)&aggx1, g_aggx1);
    cudaGetSymbolAddress((void**)&z,     g_z);
    cudaGetSymbolAddress((void**)&h,     g_h);
    cudaGetSymbolAddress((void**)&cnt2,  g_cnt2);
    cudaGetSymbolAddress((void**)&off2,  g_off2);
    cudaGetSymbolAddress((void**)&pos2,  g_pos2);
    cudaGetSymbolAddress((void**)&adj2,  g_adj2);
    cudaGetSymbolAddress((void**)&aggh2, g_aggh2);
    cudaGetSymbolAddress((void**)&blk,   g_blk);
    cudaGetSymbolAddress((void**)&fS1,   g_fS1);
    cudaGetSymbolAddress((void**)&fD1,   g_fD1);
    cudaGetSymbolAddress((void**)&fO1,   g_fO1);
    cudaGetSymbolAddress((void**)&fS2,   g_fS2);
    cudaGetSymbolAddress((void**)&fD2,   g_fD2);
    cudaGetSymbolAddress((void**)&fO2,   g_fO2);

    float* out = (float*)d_out;

    // dynamic smem sizes
    constexpr int SM_DUAL = (128 * 132 + 2 * 128 * 64) * 4;   // 133120
    constexpr int SM_RELU = (128 * 68  + 64 * 128)     * 4;   // 67584
    constexpr int SM_BIAS = (128 * 68  + 64 * 64)      * 4;   // 51200
    cudaFuncSetAttribute(mma_gemm<128, 64, 0>, cudaFuncAttributeMaxDynamicSharedMemorySize, SM_DUAL);
    cudaFuncSetAttribute(mma_gemm<64, 128, 1>, cudaFuncAttributeMaxDynamicSharedMemorySize, SM_RELU);
    cudaFuncSetAttribute(mma_gemm<64, 64, 2>,  cudaFuncAttributeMaxDynamicSharedMemorySize, SM_BIAS);

    // weight fragment prep (independent of everything else)
    prep_frags<<<(45056 + 255) / 256, 256>>>(W_src1, W_dst1, W_out1, W_src2, W_dst2, W_out2,
                                             fS1, fD1, fO1, fS2, fD2, fO2);

    // ======== CSR layer 1 ========
    zero_all<<<(C_N1 + 255) / 256, 256>>>(cnt1, pos1, cnt2, pos2);
    hist_kernel<<<(E1 + 255) / 256, 256>>>(dst1, cnt1, E1);
    {
        int nb = (C_N1 + 1023) / 1024;
        scan_partial<<<nb, 256>>>(cnt1, off1, blk, C_N1);
        scan_aux<<<1, 64>>>(blk, nb);
        scan_add<<<(C_N1 + 255) / 256, 256>>>(off1, blk, C_N1);
    }
    fill_adj<<<(E1 + 255) / 256, 256>>>(src1, dst1, off1, pos1, adj1, E1);
    gather_mean128<<<(C_N1 * 32 + 255) / 256, 256>>>(x, adj1, off1, cnt1, aggx1, C_N1);

    // z1 = (aggx1 @ W_src1) * (x @ W_dst1)
    mma_gemm<128, 64, 0><<<(C_N1 + 127) / 128, 256, SM_DUAL>>>(aggx1, x, fS1, fD1, nullptr, z, C_N1);
    // h = relu(z1 @ W_out1 + b1)
    mma_gemm<64, 128, 1><<<(C_N1 + 127) / 128, 256, SM_RELU>>>(z, nullptr, fO1, nullptr, b1, h, C_N1);

    // ======== CSR layer 2 ========
    hist_kernel<<<(E2 + 255) / 256, 256>>>(dst2, cnt2, E2);
    {
        int nb = (C_N2 + 1023) / 1024;
        scan_partial<<<nb, 256>>>(cnt2, off2, blk, C_N2);
        scan_aux<<<1, 64>>>(blk, nb);
        scan_add<<<(C_N2 + 255) / 256, 256>>>(off2, blk, C_N2);
    }
    fill_adj<<<(E2 + 255) / 256, 256>>>(src2, dst2, off2, pos2, adj2, E2);
    gather_mean128<<<(C_N2 * 32 + 255) / 256, 256>>>(h, adj2, off2, cnt2, aggh2, C_N2);

    // z2 = (aggh2 @ W_src2) * (h @ W_dst2)
    mma_gemm<128, 64, 0><<<(C_N2 + 127) / 128, 256, SM_DUAL>>>(aggh2, h, fS2, fD2, nullptr, z, C_N2);
    // out = z2 @ W_out2 + b2
    mma_gemm<64, 64, 2><<<(C_N2 + 127) / 128, 256, SM_BIAS>>>(z, nullptr, fO2, nullptr, b2, out, C_N2);
}

// round 6
// speedup vs baseline: 2.1444x; 1.2187x over previous
#include <cuda_runtime.h>
#include <cstdint>

// Problem constants (from reference)
#define C_N0 200000
#define C_N1 50000
#define C_N2 10000
#define C_INF 128
#define C_HID 128
#define C_RANK 64
#define C_OUTC 64
#define C_E1 800000
#define C_E2 160000
#define PAD 128

// ---------------- scratch (device globals; no allocation) ----------------
__device__ int   g_cnt1 [C_N1];
__device__ int   g_adj1 [(size_t)C_N1 * PAD];     // 25.6 MB padded slots
__device__ float g_aggx1[(size_t)C_N1 * C_INF];
__device__ float g_h    [(size_t)C_N1 * C_HID];
__device__ int   g_cnt2 [C_N2];
__device__ int   g_adj2 [(size_t)C_N2 * PAD];
__device__ float g_aggh2[(size_t)C_N2 * C_HID];

// fragment-major tf32 weight panels: [kstep][ntile][lane]{b0,b1}
__device__ float g_fS1[128 * 64];
__device__ float g_fD1[128 * 64];
__device__ float g_fO1[64 * 128];
__device__ float g_fS2[128 * 64];
__device__ float g_fD2[128 * 64];
__device__ float g_fO2[64 * 64];

// ---------------- helpers ----------------
__device__ __forceinline__ uint32_t f2tf32(float f) {
    uint32_t r;
    asm("cvt.rna.tf32.f32 %0, %1;" : "=r"(r) : "f"(f));
    return r;
}
__device__ __forceinline__ void mma_tf32(float* c, uint32_t a0, uint32_t a1,
                                         uint32_t a2, uint32_t a3,
                                         uint32_t b0, uint32_t b1) {
    asm volatile(
        "mma.sync.aligned.m16n8k8.row.col.f32.tf32.tf32.f32 "
        "{%0,%1,%2,%3}, {%4,%5,%6,%7}, {%8,%9}, {%0,%1,%2,%3};"
        : "+f"(c[0]), "+f"(c[1]), "+f"(c[2]), "+f"(c[3])
        : "r"(a0), "r"(a1), "r"(a2), "r"(a3), "r"(b0), "r"(b1));
}

// ---------------- setup: weight frag prep + zero counters ----------------
// frag idx = ((kk*(N/8)+nt)*32 + lane)*2 + p ; element = W[kk*8+(lane&3)+p*4][nt*8+(lane>>2)]
__global__ void setup_kernel(const float* __restrict__ Ws1, const float* __restrict__ Wd1,
                             const float* __restrict__ Wo1, const float* __restrict__ Ws2,
                             const float* __restrict__ Wd2, const float* __restrict__ Wo2,
                             float* __restrict__ Fs1, float* __restrict__ Fd1,
                             float* __restrict__ Fo1, float* __restrict__ Fs2,
                             float* __restrict__ Fd2, float* __restrict__ Fo2,
                             int* __restrict__ cnt1, int* __restrict__ cnt2)
{
    int i = blockIdx.x * 256 + threadIdx.x;
    if (i < C_N1) cnt1[i] = 0;
    if (i < C_N2) cnt2[i] = 0;
    if (i >= 45056) return;
    const float* W; float* F; int N, idx;
    if      (i < 8192)  { W = Ws1; F = Fs1; N = 64;  idx = i; }
    else if (i < 16384) { W = Wd1; F = Fd1; N = 64;  idx = i - 8192; }
    else if (i < 24576) { W = Wo1; F = Fo1; N = 128; idx = i - 16384; }
    else if (i < 32768) { W = Ws2; F = Fs2; N = 64;  idx = i - 24576; }
    else if (i < 40960) { W = Wd2; F = Fd2; N = 64;  idx = i - 32768; }
    else                { W = Wo2; F = Fo2; N = 64;  idx = i - 40960; }
    int p    = idx & 1;
    int lane = (idx >> 1) & 31;
    int t    = idx >> 6;
    int NT   = N / 8;
    int nt   = t % NT;
    int kk   = t / NT;
    int k = kk * 8 + (lane & 3) + p * 4;
    int n = nt * 8 + (lane >> 2);
    F[idx] = __uint_as_float(f2tf32(W[k * N + n]));
}

// ---------------- padded adjacency fill (replaces hist+scan+fill) --------
__global__ void fill_pad(const int* __restrict__ src, const int* __restrict__ dst,
                         int* __restrict__ cnt, int* __restrict__ adj, int E)
{
    int e = blockIdx.x * blockDim.x + threadIdx.x;
    if (e >= E) return;
    int d = dst[e];
    int p = atomicAdd(&cnt[d], 1);
    if (p < PAD) adj[(size_t)d * PAD + p] = src[e];
}

// ---------------- gather-mean over 128-dim features ----------------------
__global__ void gather_mean128(const float* __restrict__ feat,
                               const int* __restrict__ adj,
                               const int* __restrict__ cnt,
                               float* __restrict__ out, int Ndst)
{
    int warp = (blockIdx.x * blockDim.x + threadIdx.x) >> 5;
    int lane = threadIdx.x & 31;
    if (warp >= Ndst) return;
    const int* ap = &adj[(size_t)warp * PAD];
    int cn = cnt[warp];
    int c  = min(cn, PAD);
    float4 acc = make_float4(0.f, 0.f, 0.f, 0.f);
    int j = 0;
    for (; j + 3 < c; j += 4) {                          // 4-deep MLP
        int s0 = __ldg(&ap[j]);
        int s1 = __ldg(&ap[j + 1]);
        int s2 = __ldg(&ap[j + 2]);
        int s3 = __ldg(&ap[j + 3]);
        float4 a = *(const float4*)&feat[(size_t)s0 * 128 + lane * 4];
        float4 b = *(const float4*)&feat[(size_t)s1 * 128 + lane * 4];
        float4 cc = *(const float4*)&feat[(size_t)s2 * 128 + lane * 4];
        float4 d = *(const float4*)&feat[(size_t)s3 * 128 + lane * 4];
        acc.x += (a.x + b.x) + (cc.x + d.x);
        acc.y += (a.y + b.y) + (cc.y + d.y);
        acc.z += (a.z + b.z) + (cc.z + d.z);
        acc.w += (a.w + b.w) + (cc.w + d.w);
    }
    for (; j < c; j++) {
        int s0 = __ldg(&ap[j]);
        float4 a = *(const float4*)&feat[(size_t)s0 * 128 + lane * 4];
        acc.x += a.x; acc.y += a.y; acc.z += a.z; acc.w += a.w;
    }
    float sc = 1.0f / fmaxf((float)cn, 1.0f);
    float4 v = make_float4(acc.x * sc, acc.y * sc, acc.z * sc, acc.w * sc);
    *(float4*)&out[(size_t)warp * 128 + lane * 4] = v;
}

// ---------------- fused layer GEMM ---------------------------------------
// C[M,NOUT] = act( ((A1@W1) * (A2@W2)) @ WO + bias )   ; K=128, rank 64
// 256 threads = 8 warps, 128-row tile, 16 rows/warp.
template <int NOUT, bool RELU>
__global__ void __launch_bounds__(256, 1)
fused_layer(const float* __restrict__ A1, const float* __restrict__ A2,
            const float* __restrict__ F1, const float* __restrict__ F2,
            const float* __restrict__ FO, const float* __restrict__ bias,
            float* __restrict__ C, int M)
{
    extern __shared__ float smem[];
    constexpr int K   = 128;
    constexpr int KP  = 132;            // pad 4 -> conflict-free A frags
    constexpr int KP2 = 68;
    constexpr int NT  = 8;              // rank 64 / 8
    constexpr int KS  = 16;             // 128 / 8
    constexpr int NT2 = NOUT / 8;

    float* As  = smem;                  // 128*132 (phase 1/2), reused 128*68 (phase 3)
    float* Bf1 = smem + 128 * KP;       // 8192
    float* Bf2 = Bf1 + 128 * 64;        // 8192
    float* BfO = Bf2 + 128 * 64;        // 64*NOUT

    const int tid  = threadIdx.x;
    const int wid  = tid >> 5;
    const int lane = tid & 31;
    const int g    = lane >> 2;
    const int tig  = lane & 3;
    const int row0 = blockIdx.x * 128;

    // copy all B fragment panels (linear float4)
    {
        const float4* s1 = (const float4*)F1;
        const float4* s2 = (const float4*)F2;
        float4* d1 = (float4*)Bf1;
        float4* d2 = (float4*)Bf2;
        #pragma unroll 4
        for (int i = tid; i < 128 * 64 / 4; i += 256) { d1[i] = s1[i]; d2[i] = s2[i]; }
        const float4* so = (const float4*)FO;
        float4* dd = (float4*)BfO;
        #pragma unroll 4
        for (int i = tid; i < 64 * NOUT / 4; i += 256) dd[i] = so[i];
    }

    // stage A1
    #pragma unroll 2
    for (int i = tid; i < 128 * (K / 4); i += 256) {
        int r = i / (K / 4);
        int c = (i % (K / 4)) * 4;
        int gr = row0 + r;
        float4 v = make_float4(0.f, 0.f, 0.f, 0.f);
        if (gr < M) v = *(const float4*)&A1[(size_t)gr * K + c];
        uint4 t;
        t.x = f2tf32(v.x); t.y = f2tf32(v.y); t.z = f2tf32(v.z); t.w = f2tf32(v.w);
        *(uint4*)&As[r * KP + c] = t;
    }
    __syncthreads();

    const float* abase = &As[(wid * 16 + g) * KP + tig];

    float accA[NT][4];
    #pragma unroll
    for (int nt = 0; nt < NT; nt++)
        { accA[nt][0] = accA[nt][1] = accA[nt][2] = accA[nt][3] = 0.f; }
    #pragma unroll
    for (int kk = 0; kk < KS; kk++) {
        uint32_t a0 = __float_as_uint(abase[kk * 8 + 0]);
        uint32_t a2 = __float_as_uint(abase[kk * 8 + 4]);
        uint32_t a1 = __float_as_uint(abase[kk * 8 + 8 * KP]);
        uint32_t a3 = __float_as_uint(abase[kk * 8 + 8 * KP + 4]);
        const float2* bf = (const float2*)Bf1 + (size_t)(kk * NT) * 32 + lane;
        #pragma unroll
        for (int nt = 0; nt < NT; nt++) {
            float2 b = bf[nt * 32];
            mma_tf32(accA[nt], a0, a1, a2, a3,
                     __float_as_uint(b.x), __float_as_uint(b.y));
        }
    }

    __syncthreads();
    // stage A2 into same buffer
    #pragma unroll 2
    for (int i = tid; i < 128 * (K / 4); i += 256) {
        int r = i / (K / 4);
        int c = (i % (K / 4)) * 4;
        int gr = row0 + r;
        float4 v = make_float4(0.f, 0.f, 0.f, 0.f);
        if (gr < M) v = *(const float4*)&A2[(size_t)gr * K + c];
        uint4 t;
        t.x = f2tf32(v.x); t.y = f2tf32(v.y); t.z = f2tf32(v.z); t.w = f2tf32(v.w);
        *(uint4*)&As[r * KP + c] = t;
    }
    __syncthreads();

    float accB[NT][4];
    #pragma unroll
    for (int nt = 0; nt < NT; nt++)
        { accB[nt][0] = accB[nt][1] = accB[nt][2] = accB[nt][3] = 0.f; }
    #pragma unroll
    for (int kk = 0; kk < KS; kk++) {
        uint32_t a0 = __float_as_uint(abase[kk * 8 + 0]);
        uint32_t a2 = __float_as_uint(abase[kk * 8 + 4]);
        uint32_t a1 = __float_as_uint(abase[kk * 8 + 8 * KP]);
        uint32_t a3 = __float_as_uint(abase[kk * 8 + 8 * KP + 4]);
        const float2* bf = (const float2*)Bf2 + (size_t)(kk * NT) * 32 + lane;
        #pragma unroll
        for (int nt = 0; nt < NT; nt++) {
            float2 b = bf[nt * 32];
            mma_tf32(accB[nt], a0, a1, a2, a3,
                     __float_as_uint(b.x), __float_as_uint(b.y));
        }
    }

    __syncthreads();
    // z = accA * accB -> smem (tf32, padded KP2), fragment rows local
    {
        const int lr0 = wid * 16 + g;
        #pragma unroll
        for (int nt = 0; nt < NT; nt++) {
            int col = nt * 8 + 2 * tig;
            uint2 v0, v1;
            v0.x = f2tf32(accA[nt][0] * accB[nt][0]);
            v0.y = f2tf32(accA[nt][1] * accB[nt][1]);
            v1.x = f2tf32(accA[nt][2] * accB[nt][2]);
            v1.y = f2tf32(accA[nt][3] * accB[nt][3]);
            *(uint2*)&As[lr0 * KP2 + col]       = v0;
            *(uint2*)&As[(lr0 + 8) * KP2 + col] = v1;
        }
    }
    __syncthreads();

    // phase 3: (z @ WO + bias), K=64
    float acc2[NT2][4];
    #pragma unroll
    for (int nt = 0; nt < NT2; nt++)
        { acc2[nt][0] = acc2[nt][1] = acc2[nt][2] = acc2[nt][3] = 0.f; }
    const float* abase2 = &As[(wid * 16 + g) * KP2 + tig];
    #pragma unroll
    for (int kk = 0; kk < 8; kk++) {
        uint32_t a0 = __float_as_uint(abase2[kk * 8 + 0]);
        uint32_t a2 = __float_as_uint(abase2[kk * 8 + 4]);
        uint32_t a1 = __float_as_uint(abase2[kk * 8 + 8 * KP2]);
        uint32_t a3 = __float_as_uint(abase2[kk * 8 + 8 * KP2 + 4]);
        const float2* bf = (const float2*)BfO + (size_t)(kk * NT2) * 32 + lane;
        #pragma unroll
        for (int nt = 0; nt < NT2; nt++) {
            float2 b = bf[nt * 32];
            mma_tf32(acc2[nt], a0, a1, a2, a3,
                     __float_as_uint(b.x), __float_as_uint(b.y));
        }
    }

    // epilogue
    const int r0 = row0 + wid * 16 + g;
    const int r1 = r0 + 8;
    #pragma unroll
    for (int nt = 0; nt < NT2; nt++) {
        int col = nt * 8 + 2 * tig;
        float2 bb = *(const float2*)&bias[col];
        float2 v0 = make_float2(acc2[nt][0] + bb.x, acc2[nt][1] + bb.y);
        float2 v1 = make_float2(acc2[nt][2] + bb.x, acc2[nt][3] + bb.y);
        if (RELU) {
            v0.x = fmaxf(v0.x, 0.f); v0.y = fmaxf(v0.y, 0.f);
            v1.x = fmaxf(v1.x, 0.f); v1.y = fmaxf(v1.y, 0.f);
        }
        if (r0 < M) *(float2*)&C[(size_t)r0 * NOUT + col] = v0;
        if (r1 < M) *(float2*)&C[(size_t)r1 * NOUT + col] = v1;
    }
}

// ---------------- launch ----------------
extern "C" void kernel_launch(void* const* d_in, const int* in_sizes, int n_in,
                              void* d_out, int out_size)
{
    const float* x      = (const float*)d_in[0];
    const float* W_src1 = (const float*)d_in[1];
    const float* W_dst1 = (const float*)d_in[2];
    const float* W_out1 = (const float*)d_in[3];
    const float* b1     = (const float*)d_in[4];
    const float* W_src2 = (const float*)d_in[5];
    const float* W_dst2 = (const float*)d_in[6];
    const float* W_out2 = (const float*)d_in[7];
    const float* b2     = (const float*)d_in[8];
    const int*   src1   = (const int*)d_in[9];
    const int*   dst1   = (const int*)d_in[10];
    const int*   src2   = (const int*)d_in[11];
    const int*   dst2   = (const int*)d_in[12];
    const int E1 = in_sizes[9];
    const int E2 = in_sizes[11];

    int *cnt1, *adj1, *cnt2, *adj2;
    float *aggx1, *h, *aggh2;
    float *fS1, *fD1, *fO1, *fS2, *fD2, *fO2;
    cudaGetSymbolAddress((void**)&cnt1,  g_cnt1);
    cudaGetSymbolAddress((void**)&adj1,  g_adj1);
    cudaGetSymbolAddress((void**)&aggx1, g_aggx1);
    cudaGetSymbolAddress((void**)&h,     g_h);
    cudaGetSymbolAddress((void**)&cnt2,  g_cnt2);
    cudaGetSymbolAddress((void**)&adj2,  g_adj2);
    cudaGetSymbolAddress((void**)&aggh2, g_aggh2);
    cudaGetSymbolAddress((void**)&fS1,   g_fS1);
    cudaGetSymbolAddress((void**)&fD1,   g_fD1);
    cudaGetSymbolAddress((void**)&fO1,   g_fO1);
    cudaGetSymbolAddress((void**)&fS2,   g_fS2);
    cudaGetSymbolAddress((void**)&fD2,   g_fD2);
    cudaGetSymbolAddress((void**)&fO2,   g_fO2);

    float* out = (float*)d_out;

    constexpr int SM_L1 = (128 * 132 + 2 * 128 * 64 + 64 * 128) * 4;   // 165888
    constexpr int SM_L2 = (128 * 132 + 2 * 128 * 64 + 64 * 64)  * 4;   // 149504
    cudaFuncSetAttribute(fused_layer<128, true>, cudaFuncAttributeMaxDynamicSharedMemorySize, SM_L1);
    cudaFuncSetAttribute(fused_layer<64, false>, cudaFuncAttributeMaxDynamicSharedMemorySize, SM_L2);

    // 1. setup: frag prep + zero counters
    setup_kernel<<<(50000 + 255) / 256, 256>>>(W_src1, W_dst1, W_out1, W_src2, W_dst2, W_out2,
                                               fS1, fD1, fO1, fS2, fD2, fO2, cnt1, cnt2);
    // 2. layer-1 adjacency
    fill_pad<<<(E1 + 255) / 256, 256>>>(src1, dst1, cnt1, adj1, E1);
    // 3. aggx1 = segment_mean(x)
    gather_mean128<<<(C_N1 * 32 + 255) / 256, 256>>>(x, adj1, cnt1, aggx1, C_N1);
    // 4. h = relu( ((aggx1@Ws1)*(x@Wd1)) @ Wo1 + b1 )
    fused_layer<128, true><<<(C_N1 + 127) / 128, 256, SM_L1>>>(aggx1, x, fS1, fD1, fO1, b1, h, C_N1);
    // 5. layer-2 adjacency
    fill_pad<<<(E2 + 255) / 256, 256>>>(src2, dst2, cnt2, adj2, E2);
    // 6. aggh2 = segment_mean(h)
    gather_mean128<<<(C_N2 * 32 + 255) / 256, 256>>>(h, adj2, cnt2, aggh2, C_N2);
    // 7. out = ((aggh2@Ws2)*(h@Wd2)) @ Wo2 + b2
    fused_layer<64, false><<<(C_N2 + 127) / 128, 256, SM_L2>>>(aggh2, h, fS2, fD2, fO2, b2, out, C_N2);
}

// round 7
// speedup vs baseline: 2.3549x; 1.0981x over previous
#include <cuda_runtime.h>
#include <cstdint>

// Problem constants (from reference)
#define C_N0 200000
#define C_N1 50000
#define C_N2 10000
#define C_INF 128
#define C_HID 128
#define C_RANK 64
#define C_OUTC 64
#define C_E1 800000
#define C_E2 160000
#define PAD 128

// ---------------- scratch (device globals; no allocation) ----------------
__device__ int   g_cnt1 [C_N1];
__device__ int   g_adj1 [(size_t)C_N1 * PAD];
__device__ float g_aggx1[(size_t)C_N1 * C_INF];
__device__ float g_h    [(size_t)C_N1 * C_HID];
__device__ int   g_cnt2 [C_N2];
__device__ int   g_adj2 [(size_t)C_N2 * PAD];
__device__ float g_aggh2[(size_t)C_N2 * C_HID];

// fragment-major tf32 weight panels: [kstep][ntile][lane]{b0,b1}
__device__ float g_fS1[128 * 64];
__device__ float g_fD1[128 * 64];
__device__ float g_fO1[64 * 128];
__device__ float g_fS2[128 * 64];
__device__ float g_fD2[128 * 64];
__device__ float g_fO2[64 * 64];

// ---------------- helpers ----------------
__device__ __forceinline__ uint32_t f2tf32(float f) {
    uint32_t r;
    asm("cvt.rna.tf32.f32 %0, %1;" : "=r"(r) : "f"(f));
    return r;
}
__device__ __forceinline__ void mma_tf32(float* c, uint32_t a0, uint32_t a1,
                                         uint32_t a2, uint32_t a3,
                                         uint32_t b0, uint32_t b1) {
    asm volatile(
        "mma.sync.aligned.m16n8k8.row.col.f32.tf32.tf32.f32 "
        "{%0,%1,%2,%3}, {%4,%5,%6,%7}, {%8,%9}, {%0,%1,%2,%3};"
        : "+f"(c[0]), "+f"(c[1]), "+f"(c[2]), "+f"(c[3])
        : "r"(a0), "r"(a1), "r"(a2), "r"(a3), "r"(b0), "r"(b1));
}

// ---------------- setup: weight frag prep + zero counters ----------------
__global__ void setup_kernel(const float* __restrict__ Ws1, const float* __restrict__ Wd1,
                             const float* __restrict__ Wo1, const float* __restrict__ Ws2,
                             const float* __restrict__ Wd2, const float* __restrict__ Wo2,
                             float* __restrict__ Fs1, float* __restrict__ Fd1,
                             float* __restrict__ Fo1, float* __restrict__ Fs2,
                             float* __restrict__ Fd2, float* __restrict__ Fo2,
                             int* __restrict__ cnt1, int* __restrict__ cnt2)
{
    int i = blockIdx.x * 256 + threadIdx.x;
    if (i < C_N1) cnt1[i] = 0;
    if (i < C_N2) cnt2[i] = 0;
    if (i >= 45056) return;
    const float* W; float* F; int N, idx;
    if      (i < 8192)  { W = Ws1; F = Fs1; N = 64;  idx = i; }
    else if (i < 16384) { W = Wd1; F = Fd1; N = 64;  idx = i - 8192; }
    else if (i < 24576) { W = Wo1; F = Fo1; N = 128; idx = i - 16384; }
    else if (i < 32768) { W = Ws2; F = Fs2; N = 64;  idx = i - 24576; }
    else if (i < 40960) { W = Wd2; F = Fd2; N = 64;  idx = i - 32768; }
    else                { W = Wo2; F = Fo2; N = 64;  idx = i - 40960; }
    int p    = idx & 1;
    int lane = (idx >> 1) & 31;
    int t    = idx >> 6;
    int NT   = N / 8;
    int nt   = t % NT;
    int kk   = t / NT;
    int k = kk * 8 + (lane & 3) + p * 4;
    int n = nt * 8 + (lane >> 2);
    F[idx] = __uint_as_float(f2tf32(W[k * N + n]));
}

// ---------------- padded adjacency fill ----------------------------------
__global__ void fill_pad(const int* __restrict__ src, const int* __restrict__ dst,
                         int* __restrict__ cnt, int* __restrict__ adj, int E)
{
    int e = blockIdx.x * blockDim.x + threadIdx.x;
    if (e >= E) return;
    int d = dst[e];
    int p = atomicAdd(&cnt[d], 1);
    if (p < PAD) adj[(size_t)d * PAD + p] = src[e];
}

// ---------------- gather-mean over 128-dim features ----------------------
__global__ void gather_mean128(const float* __restrict__ feat,
                               const int* __restrict__ adj,
                               const int* __restrict__ cnt,
                               float* __restrict__ out, int Ndst)
{
    int warp = (blockIdx.x * blockDim.x + threadIdx.x) >> 5;
    int lane = threadIdx.x & 31;
    if (warp >= Ndst) return;
    const int* ap = &adj[(size_t)warp * PAD];
    int cn = cnt[warp];
    int c  = min(cn, PAD);
    float4 acc = make_float4(0.f, 0.f, 0.f, 0.f);
    int j = 0;
    for (; j + 3 < c; j += 4) {
        int s0 = __ldg(&ap[j]);
        int s1 = __ldg(&ap[j + 1]);
        int s2 = __ldg(&ap[j + 2]);
        int s3 = __ldg(&ap[j + 3]);
        float4 a = *(const float4*)&feat[(size_t)s0 * 128 + lane * 4];
        float4 b = *(const float4*)&feat[(size_t)s1 * 128 + lane * 4];
        float4 cc = *(const float4*)&feat[(size_t)s2 * 128 + lane * 4];
        float4 d = *(const float4*)&feat[(size_t)s3 * 128 + lane * 4];
        acc.x += (a.x + b.x) + (cc.x + d.x);
        acc.y += (a.y + b.y) + (cc.y + d.y);
        acc.z += (a.z + b.z) + (cc.z + d.z);
        acc.w += (a.w + b.w) + (cc.w + d.w);
    }
    for (; j < c; j++) {
        int s0 = __ldg(&ap[j]);
        float4 a = *(const float4*)&feat[(size_t)s0 * 128 + lane * 4];
        acc.x += a.x; acc.y += a.y; acc.z += a.z; acc.w += a.w;
    }
    float sc = 1.0f / fmaxf((float)cn, 1.0f);
    float4 v = make_float4(acc.x * sc, acc.y * sc, acc.z * sc, acc.w * sc);
    *(float4*)&out[(size_t)warp * 128 + lane * 4] = v;
}

// ---------------- fused layer GEMM ---------------------------------------
// C[M,NOUT] = act( ((A1@W1) * (A2@W2)) @ WO + bias )   ; K=128, rank 64
// 256 threads = 8 warps, 128-row tile, 16 rows/warp, 2 CTAs/SM.
// B fragments read directly from global (__ldg; L1/L2 broadcast-resident).
template <int NOUT, bool RELU>
__global__ void __launch_bounds__(256, 2)
fused_layer(const float* __restrict__ A1, const float* __restrict__ A2,
            const float* __restrict__ F1, const float* __restrict__ F2,
            const float* __restrict__ FO, const float* __restrict__ bias,
            float* __restrict__ C, int M)
{
    extern __shared__ float smem[];
    constexpr int K   = 128;
    constexpr int KP  = 132;            // pad 4 -> conflict-free A frags
    constexpr int KP2 = 68;
    constexpr int NT  = 8;              // rank 64 / 8
    constexpr int KS  = 16;             // 128 / 8
    constexpr int NT2 = NOUT / 8;       // 16 or 8
    constexpr int NH  = NT2 / 8;        // halves in phase 3 (2 or 1)

    float* As = smem;                   // 128*132 floats; reused 128*68 for z

    const int tid  = threadIdx.x;
    const int wid  = tid >> 5;
    const int lane = tid & 31;
    const int g    = lane >> 2;
    const int tig  = lane & 3;
    const int row0 = blockIdx.x * 128;

    // ---- stage A1 ----
    #pragma unroll 2
    for (int i = tid; i < 128 * (K / 4); i += 256) {
        int r = i / (K / 4);
        int c = (i % (K / 4)) * 4;
        int gr = row0 + r;
        float4 v = make_float4(0.f, 0.f, 0.f, 0.f);
        if (gr < M) v = *(const float4*)&A1[(size_t)gr * K + c];
        uint4 t;
        t.x = f2tf32(v.x); t.y = f2tf32(v.y); t.z = f2tf32(v.z); t.w = f2tf32(v.w);
        *(uint4*)&As[r * KP + c] = t;
    }
    __syncthreads();

    const float* abase = &As[(wid * 16 + g) * KP + tig];
    const float2* bf1 = (const float2*)F1;
    const float2* bf2 = (const float2*)F2;
    const float2* bfo = (const float2*)FO;

    float accA[NT][4];
    #pragma unroll
    for (int nt = 0; nt < NT; nt++)
        { accA[nt][0] = accA[nt][1] = accA[nt][2] = accA[nt][3] = 0.f; }
    #pragma unroll
    for (int kk = 0; kk < KS; kk++) {
        uint32_t a0 = __float_as_uint(abase[kk * 8 + 0]);
        uint32_t a2 = __float_as_uint(abase[kk * 8 + 4]);
        uint32_t a1 = __float_as_uint(abase[kk * 8 + 8 * KP]);
        uint32_t a3 = __float_as_uint(abase[kk * 8 + 8 * KP + 4]);
        #pragma unroll
        for (int nt = 0; nt < NT; nt++) {
            float2 b = __ldg(&bf1[(size_t)(kk * NT + nt) * 32 + lane]);
            mma_tf32(accA[nt], a0, a1, a2, a3,
                     __float_as_uint(b.x), __float_as_uint(b.y));
        }
    }

    __syncthreads();
    // ---- stage A2 into same buffer ----
    #pragma unroll 2
    for (int i = tid; i < 128 * (K / 4); i += 256) {
        int r = i / (K / 4);
        int c = (i % (K / 4)) * 4;
        int gr = row0 + r;
        float4 v = make_float4(0.f, 0.f, 0.f, 0.f);
        if (gr < M) v = *(const float4*)&A2[(size_t)gr * K + c];
        uint4 t;
        t.x = f2tf32(v.x); t.y = f2tf32(v.y); t.z = f2tf32(v.z); t.w = f2tf32(v.w);
        *(uint4*)&As[r * KP + c] = t;
    }
    __syncthreads();

    float accB[NT][4];
    #pragma unroll
    for (int nt = 0; nt < NT; nt++)
        { accB[nt][0] = accB[nt][1] = accB[nt][2] = accB[nt][3] = 0.f; }
    #pragma unroll
    for (int kk = 0; kk < KS; kk++) {
        uint32_t a0 = __float_as_uint(abase[kk * 8 + 0]);
        uint32_t a2 = __float_as_uint(abase[kk * 8 + 4]);
        uint32_t a1 = __float_as_uint(abase[kk * 8 + 8 * KP]);
        uint32_t a3 = __float_as_uint(abase[kk * 8 + 8 * KP + 4]);
        #pragma unroll
        for (int nt = 0; nt < NT; nt++) {
            float2 b = __ldg(&bf2[(size_t)(kk * NT + nt) * 32 + lane]);
            mma_tf32(accB[nt], a0, a1, a2, a3,
                     __float_as_uint(b.x), __float_as_uint(b.y));
        }
    }

    __syncthreads();
    // ---- z = accA * accB -> smem (tf32, padded KP2) ----
    {
        const int lr0 = wid * 16 + g;
        #pragma unroll
        for (int nt = 0; nt < NT; nt++) {
            int col = nt * 8 + 2 * tig;
            uint2 v0, v1;
            v0.x = f2tf32(accA[nt][0] * accB[nt][0]);
            v0.y = f2tf32(accA[nt][1] * accB[nt][1]);
            v1.x = f2tf32(accA[nt][2] * accB[nt][2]);
            v1.y = f2tf32(accA[nt][3] * accB[nt][3]);
            *(uint2*)&As[lr0 * KP2 + col]       = v0;
            *(uint2*)&As[(lr0 + 8) * KP2 + col] = v1;
        }
    }
    __syncthreads();

    // ---- phase 3: (z @ WO + bias), K=64, NH halves of 8 ntiles ----
    const float* abase2 = &As[(wid * 16 + g) * KP2 + tig];
    const int r0 = row0 + wid * 16 + g;
    const int r1 = r0 + 8;

    #pragma unroll
    for (int nh = 0; nh < NH; nh++) {
        float acc2[8][4];
        #pragma unroll
        for (int nt = 0; nt < 8; nt++)
            { acc2[nt][0] = acc2[nt][1] = acc2[nt][2] = acc2[nt][3] = 0.f; }
        #pragma unroll
        for (int kk = 0; kk < 8; kk++) {
            uint32_t a0 = __float_as_uint(abase2[kk * 8 + 0]);
            uint32_t a2 = __float_as_uint(abase2[kk * 8 + 4]);
            uint32_t a1 = __float_as_uint(abase2[kk * 8 + 8 * KP2]);
            uint32_t a3 = __float_as_uint(abase2[kk * 8 + 8 * KP2 + 4]);
            #pragma unroll
            for (int nt = 0; nt < 8; nt++) {
                float2 b = __ldg(&bfo[(size_t)(kk * NT2 + nh * 8 + nt) * 32 + lane]);
                mma_tf32(acc2[nt], a0, a1, a2, a3,
                         __float_as_uint(b.x), __float_as_uint(b.y));
            }
        }
        // epilogue for this half
        #pragma unroll
        for (int nt = 0; nt < 8; nt++) {
            int col = (nh * 8 + nt) * 8 + 2 * tig;
            float2 bb = *(const float2*)&bias[col];
            float2 v0 = make_float2(acc2[nt][0] + bb.x, acc2[nt][1] + bb.y);
            float2 v1 = make_float2(acc2[nt][2] + bb.x, acc2[nt][3] + bb.y);
            if (RELU) {
                v0.x = fmaxf(v0.x, 0.f); v0.y = fmaxf(v0.y, 0.f);
                v1.x = fmaxf(v1.x, 0.f); v1.y = fmaxf(v1.y, 0.f);
            }
            if (r0 < M) *(float2*)&C[(size_t)r0 * NOUT + col] = v0;
            if (r1 < M) *(float2*)&C[(size_t)r1 * NOUT + col] = v1;
        }
    }
}

// ---------------- launch ----------------
extern "C" void kernel_launch(void* const* d_in, const int* in_sizes, int n_in,
                              void* d_out, int out_size)
{
    const float* x      = (const float*)d_in[0];
    const float* W_src1 = (const float*)d_in[1];
    const float* W_dst1 = (const float*)d_in[2];
    const float* W_out1 = (const float*)d_in[3];
    const float* b1     = (const float*)d_in[4];
    const float* W_src2 = (const float*)d_in[5];
    const float* W_dst2 = (const float*)d_in[6];
    const float* W_out2 = (const float*)d_in[7];
    const float* b2     = (const float*)d_in[8];
    const int*   src1   = (const int*)d_in[9];
    const int*   dst1   = (const int*)d_in[10];
    const int*   src2   = (const int*)d_in[11];
    const int*   dst2   = (const int*)d_in[12];
    const int E1 = in_sizes[9];
    const int E2 = in_sizes[11];

    int *cnt1, *adj1, *cnt2, *adj2;
    float *aggx1, *h, *aggh2;
    float *fS1, *fD1, *fO1, *fS2, *fD2, *fO2;
    cudaGetSymbolAddress((void**)&cnt1,  g_cnt1);
    cudaGetSymbolAddress((void**)&adj1,  g_adj1);
    cudaGetSymbolAddress((void**)&aggx1, g_aggx1);
    cudaGetSymbolAddress((void**)&h,     g_h);
    cudaGetSymbolAddress((void**)&cnt2,  g_cnt2);
    cudaGetSymbolAddress((void**)&adj2,  g_adj2);
    cudaGetSymbolAddress((void**)&aggh2, g_aggh2);
    cudaGetSymbolAddress((void**)&fS1,   g_fS1);
    cudaGetSymbolAddress((void**)&fD1,   g_fD1);
    cudaGetSymbolAddress((void**)&fO1,   g_fO1);
    cudaGetSymbolAddress((void**)&fS2,   g_fS2);
    cudaGetSymbolAddress((void**)&fD2,   g_fD2);
    cudaGetSymbolAddress((void**)&fO2,   g_fO2);

    float* out = (float*)d_out;

    constexpr int SM_FUSED = 128 * 132 * 4;   // 67584 bytes (A stage / z reuse)
    cudaFuncSetAttribute(fused_layer<128, true>, cudaFuncAttributeMaxDynamicSharedMemorySize, SM_FUSED);
    cudaFuncSetAttribute(fused_layer<64, false>, cudaFuncAttributeMaxDynamicSharedMemorySize, SM_FUSED);

    // 1. setup: frag prep + zero counters
    setup_kernel<<<(50000 + 255) / 256, 256>>>(W_src1, W_dst1, W_out1, W_src2, W_dst2, W_out2,
                                               fS1, fD1, fO1, fS2, fD2, fO2, cnt1, cnt2);
    // 2. layer-1 adjacency
    fill_pad<<<(E1 + 255) / 256, 256>>>(src1, dst1, cnt1, adj1, E1);
    // 3. aggx1 = segment_mean(x)
    gather_mean128<<<(C_N1 * 32 + 255) / 256, 256>>>(x, adj1, cnt1, aggx1, C_N1);
    // 4. h = relu( ((aggx1@Ws1)*(x@Wd1)) @ Wo1 + b1 )
    fused_layer<128, true><<<(C_N1 + 127) / 128, 256, SM_FUSED>>>(aggx1, x, fS1, fD1, fO1, b1, h, C_N1);
    // 5. layer-2 adjacency
    fill_pad<<<(E2 + 255) / 256, 256>>>(src2, dst2, cnt2, adj2, E2);
    // 6. aggh2 = segment_mean(h)
    gather_mean128<<<(C_N2 * 32 + 255) / 256, 256>>>(h, adj2, cnt2, aggh2, C_N2);
    // 7. out = ((aggh2@Ws2)*(h@Wd2)) @ Wo2 + b2
    fused_layer<64, false><<<(C_N2 + 127) / 128, 256, SM_FUSED>>>(aggh2, h, fS2, fD2, fO2, b2, out, C_N2);
}

// round 8
// speedup vs baseline: 2.5325x; 1.0754x over previous
#include <cuda_runtime.h>
#include <cstdint>

// Problem constants (from reference)
#define C_N0 200000
#define C_N1 50000
#define C_N2 10000
#define C_INF 128
#define C_HID 128
#define C_RANK 64
#define C_OUTC 64
#define C_E1 800000
#define C_E2 160000
#define PAD 128

// ---------------- scratch (device globals; no allocation) ----------------
__device__ int   g_cnt1 [C_N1];
__device__ __align__(16) int   g_adj1 [(size_t)C_N1 * PAD];
__device__ __align__(16) float g_aggx1[(size_t)C_N1 * C_INF];
__device__ __align__(16) float g_h    [(size_t)C_N1 * C_HID];
__device__ int   g_cnt2 [C_N2];
__device__ __align__(16) int   g_adj2 [(size_t)C_N2 * PAD];
__device__ __align__(16) float g_aggh2[(size_t)C_N2 * C_HID];

// fragment-major tf32 weight panels: [kstep][ntile][lane]{b0,b1}
__device__ __align__(16) float g_fS1[128 * 64];
__device__ __align__(16) float g_fD1[128 * 64];
__device__ __align__(16) float g_fO1[64 * 128];
__device__ __align__(16) float g_fS2[128 * 64];
__device__ __align__(16) float g_fD2[128 * 64];
__device__ __align__(16) float g_fO2[64 * 64];

// ---------------- helpers ----------------
__device__ __forceinline__ uint32_t smem_u32(const void* p) {
    uint32_t a;
    asm("{ .reg .u64 t; cvta.to.shared.u64 t, %1; cvt.u32.u64 %0, t; }" : "=r"(a) : "l"(p));
    return a;
}
__device__ __forceinline__ uint32_t f2tf32(float f) {
    uint32_t r;
    asm("cvt.rna.tf32.f32 %0, %1;" : "=r"(r) : "f"(f));
    return r;
}
__device__ __forceinline__ void mma_tf32(float* c, uint32_t a0, uint32_t a1,
                                         uint32_t a2, uint32_t a3,
                                         uint32_t b0, uint32_t b1) {
    asm volatile(
        "mma.sync.aligned.m16n8k8.row.col.f32.tf32.tf32.f32 "
        "{%0,%1,%2,%3}, {%4,%5,%6,%7}, {%8,%9}, {%0,%1,%2,%3};"
        : "+f"(c[0]), "+f"(c[1]), "+f"(c[2]), "+f"(c[3])
        : "r"(a0), "r"(a1), "r"(a2), "r"(a3), "r"(b0), "r"(b1));
}
__device__ __forceinline__ void cp16(uint32_t dst, const void* src, int sz) {
    asm volatile("cp.async.cg.shared.global [%0], [%1], 16, %2;"
                 :: "r"(dst), "l"(src), "r"(sz));
}
__device__ __forceinline__ void cp_commit_wait() {
    asm volatile("cp.async.commit_group;");
    asm volatile("cp.async.wait_group 0;");
}

// ---------------- setup: weight frag prep + zero counters ----------------
__global__ void setup_kernel(const float* __restrict__ Ws1, const float* __restrict__ Wd1,
                             const float* __restrict__ Wo1, const float* __restrict__ Ws2,
                             const float* __restrict__ Wd2, const float* __restrict__ Wo2,
                             float* __restrict__ Fs1, float* __restrict__ Fd1,
                             float* __restrict__ Fo1, float* __restrict__ Fs2,
                             float* __restrict__ Fd2, float* __restrict__ Fo2,
                             int* __restrict__ cnt1, int* __restrict__ cnt2)
{
    int i = blockIdx.x * 256 + threadIdx.x;
    if (i < C_N1) cnt1[i] = 0;
    if (i < C_N2) cnt2[i] = 0;
    if (i >= 45056) return;
    const float* W; float* F; int N, idx;
    if      (i < 8192)  { W = Ws1; F = Fs1; N = 64;  idx = i; }
    else if (i < 16384) { W = Wd1; F = Fd1; N = 64;  idx = i - 8192; }
    else if (i < 24576) { W = Wo1; F = Fo1; N = 128; idx = i - 16384; }
    else if (i < 32768) { W = Ws2; F = Fs2; N = 64;  idx = i - 24576; }
    else if (i < 40960) { W = Wd2; F = Fd2; N = 64;  idx = i - 32768; }
    else                { W = Wo2; F = Fo2; N = 64;  idx = i - 40960; }
    int p    = idx & 1;
    int lane = (idx >> 1) & 31;
    int t    = idx >> 6;
    int NT   = N / 8;
    int nt   = t % NT;
    int kk   = t / NT;
    int k = kk * 8 + (lane & 3) + p * 4;
    int n = nt * 8 + (lane >> 2);
    F[idx] = __uint_as_float(f2tf32(W[k * N + n]));
}

// ---------------- padded adjacency fill ----------------------------------
__global__ void fill_pad(const int* __restrict__ src, const int* __restrict__ dst,
                         int* __restrict__ cnt, int* __restrict__ adj, int E)
{
    int e = blockIdx.x * blockDim.x + threadIdx.x;
    if (e >= E) return;
    int d = dst[e];
    int p = atomicAdd(&cnt[d], 1);
    if (p < PAD) adj[(size_t)d * PAD + p] = src[e];
}

// ---------------- gather-mean over 128-dim features (8-deep MLP) ---------
__global__ void gather_mean128(const float* __restrict__ feat,
                               const int* __restrict__ adj,
                               const int* __restrict__ cnt,
                               float* __restrict__ out, int Ndst)
{
    int warp = (blockIdx.x * blockDim.x + threadIdx.x) >> 5;
    int lane = threadIdx.x & 31;
    if (warp >= Ndst) return;
    const int* ap = &adj[(size_t)warp * PAD];
    int cn = cnt[warp];
    int c  = min(cn, PAD);
    float4 acc = make_float4(0.f, 0.f, 0.f, 0.f);
    int j = 0;
    for (; j + 7 < c; j += 8) {
        int s[8];
        #pragma unroll
        for (int u = 0; u < 8; u++) s[u] = __ldg(&ap[j + u]);
        float4 v[8];
        #pragma unroll
        for (int u = 0; u < 8; u++)
            v[u] = *(const float4*)&feat[(size_t)s[u] * 128 + lane * 4];
        #pragma unroll
        for (int u = 0; u < 8; u++) {
            acc.x += v[u].x; acc.y += v[u].y; acc.z += v[u].z; acc.w += v[u].w;
        }
    }
    for (; j + 3 < c; j += 4) {
        int s[4];
        #pragma unroll
        for (int u = 0; u < 4; u++) s[u] = __ldg(&ap[j + u]);
        #pragma unroll
        for (int u = 0; u < 4; u++) {
            float4 v = *(const float4*)&feat[(size_t)s[u] * 128 + lane * 4];
            acc.x += v.x; acc.y += v.y; acc.z += v.z; acc.w += v.w;
        }
    }
    for (; j < c; j++) {
        int s0 = __ldg(&ap[j]);
        float4 a = *(const float4*)&feat[(size_t)s0 * 128 + lane * 4];
        acc.x += a.x; acc.y += a.y; acc.z += a.z; acc.w += a.w;
    }
    float sc = 1.0f / fmaxf((float)cn, 1.0f);
    float4 v = make_float4(acc.x * sc, acc.y * sc, acc.z * sc, acc.w * sc);
    *(float4*)&out[(size_t)warp * 128 + lane * 4] = v;
}

// ---------------- fused layer GEMM ---------------------------------------
// C[M,NOUT] = act( ((A1@W1) * (A2@W2)) @ WO + bias ) ; K=128, rank 64.
// CTA: 128 threads = 4 warps, 64-row tile, 2 CTAs/SM.
// B1/B2 fragment panels in smem (conflict-free LDS.64); WO panel via __ldg.
// A staged raw fp32 via cp.async; tf32 cvt at fragment-load time.
template <int NOUT, bool RELU>
__global__ void __launch_bounds__(128, 2)
fused_layer(const float* __restrict__ A1, const float* __restrict__ A2,
            const float* __restrict__ F1, const float* __restrict__ F2,
            const float* __restrict__ FO, const float* __restrict__ bias,
            float* __restrict__ C, int M)
{
    extern __shared__ float smem[];
    constexpr int KP  = 132;            // pad 4 -> conflict-free A frags
    constexpr int KP2 = 68;
    constexpr int NT  = 8;              // rank 64 / 8
    constexpr int KS  = 16;             // 128 / 8
    constexpr int NT2 = NOUT / 8;       // 16 or 8
    constexpr int NH  = NT2 / 8;        // phase-3 halves (2 or 1)

    float* As  = smem;                  // 64*132 floats (raw fp32 A; z reuse 64*68)
    float* Bs1 = smem + 64 * KP;        // 8192 floats
    float* Bs2 = Bs1 + 8192;            // 8192 floats

    const int tid  = threadIdx.x;
    const int wid  = tid >> 5;
    const int lane = tid & 31;
    const int g    = lane >> 2;
    const int tig  = lane & 3;
    const int row0 = blockIdx.x * 64;

    const uint32_t sA  = smem_u32(As);
    const uint32_t sB1 = smem_u32(Bs1);
    const uint32_t sB2 = smem_u32(Bs2);

    // ---- async copies: B1, B2 panels + A1 tile (single group) ----
    #pragma unroll 4
    for (int i = tid; i < 2048; i += 128) cp16(sB1 + i * 16, (const char*)F1 + i * 16, 16);
    #pragma unroll 4
    for (int i = tid; i < 2048; i += 128) cp16(sB2 + i * 16, (const char*)F2 + i * 16, 16);
    #pragma unroll 4
    for (int i = tid; i < 2048; i += 128) {
        int r = i >> 5;                 // 0..63
        int c = (i & 31) << 2;          // 0..124 step 4
        int gr = row0 + r;
        int sz = (gr < M) ? 16 : 0;
        cp16(sA + (uint32_t)(r * KP + c) * 4, &A1[(size_t)gr * 128 + c], sz);
    }
    cp_commit_wait();
    __syncthreads();

    const float* abase = &As[(wid * 16 + g) * KP + tig];

    // ---- phase 1: accA = A1 @ W1 ----
    float accA[NT][4];
    #pragma unroll
    for (int nt = 0; nt < NT; nt++)
        { accA[nt][0] = accA[nt][1] = accA[nt][2] = accA[nt][3] = 0.f; }
    #pragma unroll
    for (int kk = 0; kk < KS; kk++) {
        uint32_t a0 = f2tf32(abase[kk * 8 + 0]);
        uint32_t a2 = f2tf32(abase[kk * 8 + 4]);
        uint32_t a1 = f2tf32(abase[kk * 8 + 8 * KP]);
        uint32_t a3 = f2tf32(abase[kk * 8 + 8 * KP + 4]);
        const float2* bf = (const float2*)Bs1 + (kk * NT) * 32 + lane;
        #pragma unroll
        for (int nt = 0; nt < NT; nt++) {
            float2 b = bf[nt * 32];
            mma_tf32(accA[nt], a0, a1, a2, a3,
                     __float_as_uint(b.x), __float_as_uint(b.y));
        }
    }
    __syncthreads();

    // ---- stage A2 (raw fp32, cp.async) ----
    #pragma unroll 4
    for (int i = tid; i < 2048; i += 128) {
        int r = i >> 5;
        int c = (i & 31) << 2;
        int gr = row0 + r;
        int sz = (gr < M) ? 16 : 0;
        cp16(sA + (uint32_t)(r * KP + c) * 4, &A2[(size_t)gr * 128 + c], sz);
    }
    cp_commit_wait();
    __syncthreads();

    // ---- phase 2: accB = A2 @ W2 ----
    float accB[NT][4];
    #pragma unroll
    for (int nt = 0; nt < NT; nt++)
        { accB[nt][0] = accB[nt][1] = accB[nt][2] = accB[nt][3] = 0.f; }
    #pragma unroll
    for (int kk = 0; kk < KS; kk++) {
        uint32_t a0 = f2tf32(abase[kk * 8 + 0]);
        uint32_t a2 = f2tf32(abase[kk * 8 + 4]);
        uint32_t a1 = f2tf32(abase[kk * 8 + 8 * KP]);
        uint32_t a3 = f2tf32(abase[kk * 8 + 8 * KP + 4]);
        const float2* bf = (const float2*)Bs2 + (kk * NT) * 32 + lane;
        #pragma unroll
        for (int nt = 0; nt < NT; nt++) {
            float2 b = bf[nt * 32];
            mma_tf32(accB[nt], a0, a1, a2, a3,
                     __float_as_uint(b.x), __float_as_uint(b.y));
        }
    }
    __syncthreads();   // all warps done reading A2 before z overwrites As

    // ---- z = accA * accB -> smem (tf32, padded KP2) ----
    {
        const int lr0 = wid * 16 + g;
        #pragma unroll
        for (int nt = 0; nt < NT; nt++) {
            int col = nt * 8 + 2 * tig;
            uint2 v0, v1;
            v0.x = f2tf32(accA[nt][0] * accB[nt][0]);
            v0.y = f2tf32(accA[nt][1] * accB[nt][1]);
            v1.x = f2tf32(accA[nt][2] * accB[nt][2]);
            v1.y = f2tf32(accA[nt][3] * accB[nt][3]);
            *(uint2*)&As[lr0 * KP2 + col]       = v0;
            *(uint2*)&As[(lr0 + 8) * KP2 + col] = v1;
        }
    }
    __syncthreads();

    // ---- phase 3: (z @ WO + bias), K=64, NH halves of 8 ntiles ----
    const float* abase2 = &As[(wid * 16 + g) * KP2 + tig];
    const float2* bfo = (const float2*)FO;
    const int r0 = row0 + wid * 16 + g;
    const int r1 = r0 + 8;

    #pragma unroll
    for (int nh = 0; nh < NH; nh++) {
        float acc2[8][4];
        #pragma unroll
        for (int nt = 0; nt < 8; nt++)
            { acc2[nt][0] = acc2[nt][1] = acc2[nt][2] = acc2[nt][3] = 0.f; }
        #pragma unroll
        for (int kk = 0; kk < 8; kk++) {
            // z already tf32 bits — no cvt
            uint32_t a0 = __float_as_uint(abase2[kk * 8 + 0]);
            uint32_t a2 = __float_as_uint(abase2[kk * 8 + 4]);
            uint32_t a1 = __float_as_uint(abase2[kk * 8 + 8 * KP2]);
            uint32_t a3 = __float_as_uint(abase2[kk * 8 + 8 * KP2 + 4]);
            #pragma unroll
            for (int nt = 0; nt < 8; nt++) {
                float2 b = __ldg(&bfo[(size_t)(kk * NT2 + nh * 8 + nt) * 32 + lane]);
                mma_tf32(acc2[nt], a0, a1, a2, a3,
                         __float_as_uint(b.x), __float_as_uint(b.y));
            }
        }
        #pragma unroll
        for (int nt = 0; nt < 8; nt++) {
            int col = (nh * 8 + nt) * 8 + 2 * tig;
            float2 bb = *(const float2*)&bias[col];
            float2 v0 = make_float2(acc2[nt][0] + bb.x, acc2[nt][1] + bb.y);
            float2 v1 = make_float2(acc2[nt][2] + bb.x, acc2[nt][3] + bb.y);
            if (RELU) {
                v0.x = fmaxf(v0.x, 0.f); v0.y = fmaxf(v0.y, 0.f);
                v1.x = fmaxf(v1.x, 0.f); v1.y = fmaxf(v1.y, 0.f);
            }
            if (r0 < M) *(float2*)&C[(size_t)r0 * NOUT + col] = v0;
            if (r1 < M) *(float2*)&C[(size_t)r1 * NOUT + col] = v1;
        }
    }
}

// ---------------- launch ----------------
extern "C" void kernel_launch(void* const* d_in, const int* in_sizes, int n_in,
                              void* d_out, int out_size)
{
    const float* x      = (const float*)d_in[0];
    const float* W_src1 = (const float*)d_in[1];
    const float* W_dst1 = (const float*)d_in[2];
    const float* W_out1 = (const float*)d_in[3];
    const float* b1     = (const float*)d_in[4];
    const float* W_src2 = (const float*)d_in[5];
    const float* W_dst2 = (const float*)d_in[6];
    const float* W_out2 = (const float*)d_in[7];
    const float* b2     = (const float*)d_in[8];
    const int*   src1   = (const int*)d_in[9];
    const int*   dst1   = (const int*)d_in[10];
    const int*   src2   = (const int*)d_in[11];
    const int*   dst2   = (const int*)d_in[12];
    const int E1 = in_sizes[9];
    const int E2 = in_sizes[11];

    int *cnt1, *adj1, *cnt2, *adj2;
    float *aggx1, *h, *aggh2;
    float *fS1, *fD1, *fO1, *fS2, *fD2, *fO2;
    cudaGetSymbolAddress((void**)&cnt1,  g_cnt1);
    cudaGetSymbolAddress((void**)&adj1,  g_adj1);
    cudaGetSymbolAddress((void**)&aggx1, g_aggx1);
    cudaGetSymbolAddress((void**)&h,     g_h);
    cudaGetSymbolAddress((void**)&cnt2,  g_cnt2);
    cudaGetSymbolAddress((void**)&adj2,  g_adj2);
    cudaGetSymbolAddress((void**)&aggh2, g_aggh2);
    cudaGetSymbolAddress((void**)&fS1,   g_fS1);
    cudaGetSymbolAddress((void**)&fD1,   g_fD1);
    cudaGetSymbolAddress((void**)&fO1,   g_fO1);
    cudaGetSymbolAddress((void**)&fS2,   g_fS2);
    cudaGetSymbolAddress((void**)&fD2,   g_fD2);
    cudaGetSymbolAddress((void**)&fO2,   g_fO2);

    float* out = (float*)d_out;

    // smem: A 64*132*4 + B1 32768 + B2 32768 = 99328 bytes -> 2 CTAs/SM
    constexpr int SM_FUSED = 64 * 132 * 4 + 2 * 32768;
    cudaFuncSetAttribute(fused_layer<128, true>, cudaFuncAttributeMaxDynamicSharedMemorySize, SM_FUSED);
    cudaFuncSetAttribute(fused_layer<64, false>, cudaFuncAttributeMaxDynamicSharedMemorySize, SM_FUSED);

    // 1. setup: frag prep + zero counters
    setup_kernel<<<(50000 + 255) / 256, 256>>>(W_src1, W_dst1, W_out1, W_src2, W_dst2, W_out2,
                                               fS1, fD1, fO1, fS2, fD2, fO2, cnt1, cnt2);
    // 2. layer-1 adjacency
    fill_pad<<<(E1 + 255) / 256, 256>>>(src1, dst1, cnt1, adj1, E1);
    // 3. aggx1 = segment_mean(x)
    gather_mean128<<<(C_N1 * 32 + 255) / 256, 256>>>(x, adj1, cnt1, aggx1, C_N1);
    // 4. h = relu( ((aggx1@Ws1)*(x@Wd1)) @ Wo1 + b1 )
    fused_layer<128, true><<<(C_N1 + 63) / 64, 128, SM_FUSED>>>(aggx1, x, fS1, fD1, fO1, b1, h, C_N1);
    // 5. layer-2 adjacency
    fill_pad<<<(E2 + 255) / 256, 256>>>(src2, dst2, cnt2, adj2, E2);
    // 6. aggh2 = segment_mean(h)
    gather_mean128<<<(C_N2 * 32 + 255) / 256, 256>>>(h, adj2, cnt2, aggh2, C_N2);
    // 7. out = ((aggh2@Ws2)*(h@Wd2)) @ Wo2 + b2
    fused_layer<64, false><<<(C_N2 + 63) / 64, 128, SM_FUSED>>>(aggh2, h, fS2, fD2, fO2, b2, out, C_N2);
}